// round 3
// baseline (speedup 1.0000x reference)
#include <cuda_runtime.h>

typedef unsigned long long ull;

#define NN 100000
#define EE 1200000
#define ET (EE + NN)

// ---------------- scratch (static device memory: allocation-free) ----------
__device__ float g_xw[NN * 128];   // post-GEMM features (xw), per layer
__device__ float g_h[NN * 128];    // aggregated layer output (GEMM input)
__device__ float g_ssrc[NN * 4];
__device__ float g_sdst[NN * 4];
__device__ int   g_cnt[NN];
__device__ int   g_off[NN + 1];
__device__ int   g_cur[NN];
__device__ int   g_csr[ET];
__device__ int   g_bsum[128];
__device__ unsigned g_gmaxu[4];

// ---------------- helpers ----------------------------------------------------
__device__ __forceinline__ ull pk2(float x, float y) {
    ull r; asm("mov.b64 %0,{%1,%2};" : "=l"(r) : "f"(x), "f"(y)); return r;
}
__device__ __forceinline__ void fma2(ull& d, ull a, ull b) {
    asm("fma.rn.f32x2 %0,%1,%2,%0;" : "+l"(d) : "l"(a), "l"(b));
}
__device__ __forceinline__ void up2(ull v, float& x, float& y) {
    asm("mov.b64 {%0,%1},%2;" : "=f"(x), "=f"(y) : "l"(v));
}
// order-preserving float->uint encoding for atomicMax
__device__ __forceinline__ unsigned encf(float f) {
    unsigned u = __float_as_uint(f);
    return (u & 0x80000000u) ? ~u : (u | 0x80000000u);
}
__device__ __forceinline__ float decf(unsigned u) {
    return (u & 0x80000000u) ? __uint_as_float(u ^ 0x80000000u) : __uint_as_float(~u);
}

// ---------------- CSR build -------------------------------------------------
__global__ void k_init_cnt() {
    int i = blockIdx.x * blockDim.x + threadIdx.x;
    if (i < NN) g_cnt[i] = 1;  // self-loop
}

__global__ void k_count(const int* __restrict__ ei) {
    int e = blockIdx.x * blockDim.x + threadIdx.x;
    if (e < EE) atomicAdd(&g_cnt[ei[EE + e]], 1);
}

__global__ void k_scan1() {  // 98 blocks x 1024
    __shared__ int s[1024];
    int i = blockIdx.x * 1024 + threadIdx.x;
    int v = (i < NN) ? g_cnt[i] : 0;
    s[threadIdx.x] = v;
    __syncthreads();
    for (int d = 1; d < 1024; d <<= 1) {
        int t = (threadIdx.x >= d) ? s[threadIdx.x - d] : 0;
        __syncthreads();
        s[threadIdx.x] += t;
        __syncthreads();
    }
    if (i < NN) g_off[i] = s[threadIdx.x] - v;  // exclusive
    if (threadIdx.x == 1023) g_bsum[blockIdx.x] = s[1023];
}

__global__ void k_scan2() {  // 1 block x 128
    __shared__ int s[128];
    int v = (threadIdx.x < 98) ? g_bsum[threadIdx.x] : 0;
    s[threadIdx.x] = v;
    __syncthreads();
    for (int d = 1; d < 128; d <<= 1) {
        int t = (threadIdx.x >= d) ? s[threadIdx.x - d] : 0;
        __syncthreads();
        s[threadIdx.x] += t;
        __syncthreads();
    }
    g_bsum[threadIdx.x] = s[threadIdx.x] - v;  // exclusive
}

__global__ void k_scan3() {
    int i = blockIdx.x * blockDim.x + threadIdx.x;
    if (i < NN) {
        int o = g_off[i] + g_bsum[i >> 10];
        g_off[i] = o;
        g_cur[i] = o;
    }
    if (i == 0) g_off[NN] = ET;
}

__global__ void k_fill(const int* __restrict__ ei) {
    int e = blockIdx.x * blockDim.x + threadIdx.x;
    if (e < EE) {
        int s = ei[e], d = ei[EE + e];
        g_csr[atomicAdd(&g_cur[d], 1)] = s;
    } else if (e < ET) {
        int v = e - EE;
        g_csr[atomicAdd(&g_cur[v], 1)] = v;
    }
}

// ---------------- GEMM (fma.rn.f32x2) + fused attention half-scores --------
// g_xw = X @ W (X: [NN,128], W: [128,128]); also writes g_ssrc/g_sdst.
__launch_bounds__(256, 2)
__global__ void k_gemm(const float* __restrict__ Xext, const float* __restrict__ W,
                       const float* __restrict__ asrc, const float* __restrict__ adst,
                       int use_h) {
    extern __shared__ float sm[];
    float* sW = sm;           // 128*128 floats (64KB)
    float* sX = sm + 16384;   // 64*128 floats (32KB)
    const float* X = use_h ? (const float*)g_h : Xext;

    for (int i = threadIdx.x; i < 4096; i += 256)
        ((float4*)sW)[i] = ((const float4*)W)[i];

    int row0 = blockIdx.x * 64;
    for (int i = threadIdx.x; i < 2048; i += 256) {
        int r = i >> 5, c = i & 31;
        int gr = row0 + r;
        float4 v = make_float4(0.f, 0.f, 0.f, 0.f);
        if (gr < NN) v = ((const float4*)X)[gr * 32 + c];
        ((float4*)sX)[i] = v;
    }
    __syncthreads();

    int tx = threadIdx.x & 31, ty = threadIdx.x >> 5;
    int c0 = tx * 4, r0 = ty * 8;

    // acc[p][c] packs rows (r0+2p [lo], r0+2p+1 [hi]) for col c0+c
    ull acc[4][4];
#pragma unroll
    for (int p = 0; p < 4; p++)
#pragma unroll
        for (int c = 0; c < 4; c++) acc[p][c] = 0ull;

#pragma unroll 1
    for (int kb = 0; kb < 128; kb += 4) {
        float4 b[4];
#pragma unroll
        for (int j = 0; j < 4; j++) b[j] = *(const float4*)&sW[(kb + j) * 128 + c0];
        float4 A[8];
#pragma unroll
        for (int r = 0; r < 8; r++) A[r] = *(const float4*)&sX[(r0 + r) * 128 + kb];
#pragma unroll
        for (int j = 0; j < 4; j++) {
            const float* bj = (const float*)&b[j];
            ull bb[4];
#pragma unroll
            for (int c = 0; c < 4; c++) bb[c] = pk2(bj[c], bj[c]);
#pragma unroll
            for (int p = 0; p < 4; p++) {
                const float* a0 = (const float*)&A[2 * p];
                const float* a1 = (const float*)&A[2 * p + 1];
                ull ap = pk2(a0[j], a1[j]);
#pragma unroll
                for (int c = 0; c < 4; c++) fma2(acc[p][c], ap, bb[c]);
            }
        }
    }

    // unpack to per-row values
    float rv[8][4];
#pragma unroll
    for (int p = 0; p < 4; p++)
#pragma unroll
        for (int c = 0; c < 4; c++) up2(acc[p][c], rv[2 * p][c], rv[2 * p + 1][c]);

    // store xw
#pragma unroll
    for (int r = 0; r < 8; r++) {
        int gr = row0 + r0 + r;
        if (gr < NN)
            ((float4*)g_xw)[gr * 32 + tx] =
                make_float4(rv[r][0], rv[r][1], rv[r][2], rv[r][3]);
    }

    // fused half-scores: head h = tx>>3, reduce over the 8-lane column group
    int h = tx >> 3;
    float4 av = ((const float4*)asrc)[tx];
    float4 dv = ((const float4*)adst)[tx];
#pragma unroll
    for (int r = 0; r < 8; r++) {
        float ps = rv[r][0] * av.x + rv[r][1] * av.y + rv[r][2] * av.z + rv[r][3] * av.w;
        float pd = rv[r][0] * dv.x + rv[r][1] * dv.y + rv[r][2] * dv.z + rv[r][3] * dv.w;
#pragma unroll
        for (int o = 1; o < 8; o <<= 1) {
            ps += __shfl_xor_sync(0xffffffffu, ps, o);
            pd += __shfl_xor_sync(0xffffffffu, pd, o);
        }
        int gr = row0 + r0 + r;
        if ((tx & 7) == 0 && gr < NN) {
            g_ssrc[gr * 4 + h] = ps;
            g_sdst[gr * 4 + h] = pd;
        }
    }
}

// ---------------- per-head global max of s_src (softmax stability bound) ---
__global__ void k_gmax_init() {
    if (threadIdx.x < 4) g_gmaxu[threadIdx.x] = 0u;  // < enc(any finite float)
}

__global__ void k_gmax() {
    float m0 = -1e30f, m1 = -1e30f, m2 = -1e30f, m3 = -1e30f;
    for (int v = blockIdx.x * blockDim.x + threadIdx.x; v < NN;
         v += gridDim.x * blockDim.x) {
        float4 s = ((const float4*)g_ssrc)[v];
        m0 = fmaxf(m0, s.x); m1 = fmaxf(m1, s.y);
        m2 = fmaxf(m2, s.z); m3 = fmaxf(m3, s.w);
    }
#pragma unroll
    for (int o = 16; o > 0; o >>= 1) {
        m0 = fmaxf(m0, __shfl_xor_sync(0xffffffffu, m0, o));
        m1 = fmaxf(m1, __shfl_xor_sync(0xffffffffu, m1, o));
        m2 = fmaxf(m2, __shfl_xor_sync(0xffffffffu, m2, o));
        m3 = fmaxf(m3, __shfl_xor_sync(0xffffffffu, m3, o));
    }
    __shared__ unsigned smx[4];
    if (threadIdx.x < 4) smx[threadIdx.x] = 0u;
    __syncthreads();
    if ((threadIdx.x & 31) == 0) {
        atomicMax(&smx[0], encf(m0));
        atomicMax(&smx[1], encf(m1));
        atomicMax(&smx[2], encf(m2));
        atomicMax(&smx[3], encf(m3));
    }
    __syncthreads();
    if (threadIdx.x < 4) atomicMax(&g_gmaxu[threadIdx.x], smx[threadIdx.x]);
}

// ---------------- warp-per-node single-pass softmax aggregation ------------
// mh = max(0, gmax_h + s_dst[v,h]) >= leaky(s_src[u]+s_dst[v]) for all u
// (leaky-relu monotone, <= max(0,x)); softmax is shift-invariant so result
// matches the reference's exact-max version.
template <bool LAST>
__global__ void k_agg(const float* __restrict__ bias, float* __restrict__ outp) {
    int g = blockIdx.x * blockDim.x + threadIdx.x;
    int v = g >> 5, lane = g & 31;
    if (v >= NN) return;

    int offv = g_off[v];
    int deg = g_off[v + 1] - offv;

    int h2 = lane >> 3;
    float sd2 = g_sdst[v * 4 + h2];
    float mh = fmaxf(decf(g_gmaxu[h2]) + sd2, 0.f);

    float4 acc = make_float4(0.f, 0.f, 0.f, 0.f);
    float dsum = 0.f;
    for (int e = 0; e < deg; e++) {
        int u = g_csr[offv + e];
        float a = g_ssrc[u * 4 + h2] + sd2;
        a = (a > 0.f) ? a : 0.2f * a;
        float ex = __expf(a - mh);
        dsum += ex;
        float4 xu = ((const float4*)g_xw)[u * 32 + lane];
        acc.x += ex * xu.x;
        acc.y += ex * xu.y;
        acc.z += ex * xu.z;
        acc.w += ex * xu.w;
    }
    float inv = 1.f / dsum;
    acc.x *= inv; acc.y *= inv; acc.z *= inv; acc.w *= inv;

    if (!LAST) {
        float4 bv = ((const float4*)bias)[lane];
        float4 o;
        o.x = acc.x + bv.x; o.y = acc.y + bv.y;
        o.z = acc.z + bv.z; o.w = acc.w + bv.w;
        o.x = o.x > 0.f ? o.x : expm1f(o.x);
        o.y = o.y > 0.f ? o.y : expm1f(o.y);
        o.z = o.z > 0.f ? o.z : expm1f(o.z);
        o.w = o.w > 0.f ? o.w : expm1f(o.w);
        ((float4*)g_h)[v * 32 + lane] = o;
    } else {
        // mean over 4 heads: lanes {l, l+8, l+16, l+24} hold same within-head cols
        acc.x += __shfl_xor_sync(0xffffffffu, acc.x, 8);
        acc.y += __shfl_xor_sync(0xffffffffu, acc.y, 8);
        acc.z += __shfl_xor_sync(0xffffffffu, acc.z, 8);
        acc.w += __shfl_xor_sync(0xffffffffu, acc.w, 8);
        acc.x += __shfl_xor_sync(0xffffffffu, acc.x, 16);
        acc.y += __shfl_xor_sync(0xffffffffu, acc.y, 16);
        acc.z += __shfl_xor_sync(0xffffffffu, acc.z, 16);
        acc.w += __shfl_xor_sync(0xffffffffu, acc.w, 16);
        if (lane < 8) {
            float4 bv = ((const float4*)bias)[lane];
            float4 o = make_float4(acc.x * 0.25f + bv.x, acc.y * 0.25f + bv.y,
                                   acc.z * 0.25f + bv.z, acc.w * 0.25f + bv.w);
            ((float4*)outp)[v * 8 + lane] = o;
        }
    }
}

// ---------------- driver ----------------------------------------------------
extern "C" void kernel_launch(void* const* d_in, const int* in_sizes, int n_in,
                              void* d_out, int out_size) {
    const float* x   = (const float*)d_in[0];
    const int*   ei  = (const int*)d_in[1];
    const float* W1  = (const float*)d_in[2];
    const float* as1 = (const float*)d_in[3];
    const float* ad1 = (const float*)d_in[4];
    const float* b1  = (const float*)d_in[5];
    const float* W2  = (const float*)d_in[6];
    const float* as2 = (const float*)d_in[7];
    const float* ad2 = (const float*)d_in[8];
    const float* b2  = (const float*)d_in[9];
    const float* W3  = (const float*)d_in[10];
    const float* as3 = (const float*)d_in[11];
    const float* ad3 = (const float*)d_in[12];
    const float* b3  = (const float*)d_in[13];
    float* out = (float*)d_out;

    cudaFuncSetAttribute(k_gemm, cudaFuncAttributeMaxDynamicSharedMemorySize, 98304);

    // CSR by destination (rebuilt every call: deterministic work, capture-safe)
    k_init_cnt<<<(NN + 255) / 256, 256>>>();
    k_count<<<(EE + 255) / 256, 256>>>(ei);
    k_scan1<<<98, 1024>>>();
    k_scan2<<<1, 128>>>();
    k_scan3<<<(NN + 255) / 256, 256>>>();
    k_fill<<<(ET + 255) / 256, 256>>>(ei);

    const int GB = (NN + 63) / 64;   // 1563
    const int WB = NN / 8;           // 12500 blocks, warp per node

    // layer 1
    k_gemm<<<GB, 256, 98304>>>(x, W1, as1, ad1, 0);
    k_gmax_init<<<1, 32>>>();
    k_gmax<<<160, 256>>>();
    k_agg<false><<<WB, 256>>>(b1, nullptr);
    // layer 2
    k_gemm<<<GB, 256, 98304>>>(nullptr, W2, as2, ad2, 1);
    k_gmax_init<<<1, 32>>>();
    k_gmax<<<160, 256>>>();
    k_agg<false><<<WB, 256>>>(b2, nullptr);
    // layer 3 (mean over heads)
    k_gemm<<<GB, 256, 98304>>>(nullptr, W3, as3, ad3, 1);
    k_gmax_init<<<1, 32>>>();
    k_gmax<<<160, 256>>>();
    k_agg<true><<<WB, 256>>>(b3, out);
}

// round 4
// speedup vs baseline: 1.3768x; 1.3768x over previous
#include <cuda_runtime.h>

#define NN 100000
#define EE 1200000
#define ET (EE + NN)

// ---------------- scratch (static device memory: allocation-free) ----------
__device__ float g_xw[NN * 128];   // post-GEMM features (xw), per layer
__device__ float g_h[NN * 128];    // aggregated layer output (GEMM input)
__device__ float g_ssrc[NN * 4];
__device__ float g_sdst[NN * 4];
__device__ int   g_cnt[NN];        // zero-initialized at load; re-zeroed by k_fill
__device__ int   g_off[NN + 1];
__device__ int   g_cur[NN];
__device__ int   g_csr[ET];
__device__ int   g_bsum[128];
__device__ unsigned g_gmaxu[4];

// order-preserving float->uint encoding for atomicMax
__device__ __forceinline__ unsigned encf(float f) {
    unsigned u = __float_as_uint(f);
    return (u & 0x80000000u) ? ~u : (u | 0x80000000u);
}
__device__ __forceinline__ float decf(unsigned u) {
    return (u & 0x80000000u) ? __uint_as_float(u ^ 0x80000000u) : __uint_as_float(~u);
}

// ---------------- CSR build (5 launches) ------------------------------------
__global__ void k_count(const int* __restrict__ ei) {
    int e = blockIdx.x * blockDim.x + threadIdx.x;
    if (e < EE) atomicAdd(&g_cnt[ei[EE + e]], 1);
}

__global__ void k_scan1() {  // 98 blocks x 1024
    __shared__ int s[1024];
    int i = blockIdx.x * 1024 + threadIdx.x;
    int v = (i < NN) ? g_cnt[i] : 0;
    s[threadIdx.x] = v;
    __syncthreads();
    for (int d = 1; d < 1024; d <<= 1) {
        int t = (threadIdx.x >= d) ? s[threadIdx.x - d] : 0;
        __syncthreads();
        s[threadIdx.x] += t;
        __syncthreads();
    }
    if (i < NN) g_off[i] = s[threadIdx.x] - v;  // exclusive (edges only)
    if (threadIdx.x == 1023) g_bsum[blockIdx.x] = s[1023];
}

__global__ void k_scan2() {  // 1 block x 128
    __shared__ int s[128];
    int v = (threadIdx.x < 98) ? g_bsum[threadIdx.x] : 0;
    s[threadIdx.x] = v;
    __syncthreads();
    for (int d = 1; d < 128; d <<= 1) {
        int t = (threadIdx.x >= d) ? s[threadIdx.x - d] : 0;
        __syncthreads();
        s[threadIdx.x] += t;
        __syncthreads();
    }
    g_bsum[threadIdx.x] = s[threadIdx.x] - v;  // exclusive
}

__global__ void k_scan3() {
    int i = blockIdx.x * blockDim.x + threadIdx.x;
    if (i < NN) {
        // +i folds the per-node self-loop into the offsets
        int o = g_off[i] + g_bsum[i >> 10] + i;
        g_off[i] = o;
        g_cur[i] = o;
    }
    if (i == 0) g_off[NN] = ET;
}

__global__ void k_fill(const int* __restrict__ ei) {
    int e = blockIdx.x * blockDim.x + threadIdx.x;
    if (e < EE) {
        int s = ei[e], d = ei[EE + e];
        g_csr[atomicAdd(&g_cur[d], 1)] = s;
    } else if (e < ET) {
        int v = e - EE;
        g_csr[atomicAdd(&g_cur[v], 1)] = v;  // self-loop
        g_cnt[v] = 0;                        // reset for next call (deterministic)
    }
}

// ---------------- GEMM (FFMA, proven) + fused attention half-scores --------
// g_xw = X @ W (X: [NN,128], W: [128,128]); also writes g_ssrc/g_sdst.
__launch_bounds__(256, 2)
__global__ void k_gemm(const float* __restrict__ Xext, const float* __restrict__ W,
                       const float* __restrict__ asrc, const float* __restrict__ adst,
                       int use_h) {
    extern __shared__ float sm[];
    float* sW = sm;           // 128*128 floats (64KB)
    float* sX = sm + 16384;   // 64*128 floats (32KB)
    const float* X = use_h ? (const float*)g_h : Xext;

    for (int i = threadIdx.x; i < 4096; i += 256)
        ((float4*)sW)[i] = ((const float4*)W)[i];

    int row0 = blockIdx.x * 64;
    for (int i = threadIdx.x; i < 2048; i += 256) {
        int r = i >> 5, c = i & 31;
        int gr = row0 + r;
        float4 v = make_float4(0.f, 0.f, 0.f, 0.f);
        if (gr < NN) v = ((const float4*)X)[gr * 32 + c];
        ((float4*)sX)[i] = v;
    }
    __syncthreads();

    int tx = threadIdx.x & 31, ty = threadIdx.x >> 5;
    int c0 = tx * 4, r0 = ty * 8;
    float acc[8][4];
#pragma unroll
    for (int ri = 0; ri < 8; ri++) {
        acc[ri][0] = 0.f; acc[ri][1] = 0.f; acc[ri][2] = 0.f; acc[ri][3] = 0.f;
    }
#pragma unroll 4
    for (int k = 0; k < 128; k++) {
        float4 b = *(const float4*)&sW[k * 128 + c0];
#pragma unroll
        for (int ri = 0; ri < 8; ri++) {
            float a = sX[(r0 + ri) * 128 + k];
            acc[ri][0] += a * b.x;
            acc[ri][1] += a * b.y;
            acc[ri][2] += a * b.z;
            acc[ri][3] += a * b.w;
        }
    }

    // store xw
#pragma unroll
    for (int ri = 0; ri < 8; ri++) {
        int gr = row0 + r0 + ri;
        if (gr < NN)
            ((float4*)g_xw)[gr * 32 + tx] =
                make_float4(acc[ri][0], acc[ri][1], acc[ri][2], acc[ri][3]);
    }

    // fused half-scores: head h = tx>>3, reduce over the 8-lane column group
    int h = tx >> 3;
    float4 av = ((const float4*)asrc)[tx];
    float4 dv = ((const float4*)adst)[tx];
#pragma unroll
    for (int ri = 0; ri < 8; ri++) {
        float ps = acc[ri][0] * av.x + acc[ri][1] * av.y +
                   acc[ri][2] * av.z + acc[ri][3] * av.w;
        float pd = acc[ri][0] * dv.x + acc[ri][1] * dv.y +
                   acc[ri][2] * dv.z + acc[ri][3] * dv.w;
#pragma unroll
        for (int o = 1; o < 8; o <<= 1) {
            ps += __shfl_xor_sync(0xffffffffu, ps, o);
            pd += __shfl_xor_sync(0xffffffffu, pd, o);
        }
        int gr = row0 + r0 + ri;
        if ((tx & 7) == 0 && gr < NN) {
            g_ssrc[gr * 4 + h] = ps;
            g_sdst[gr * 4 + h] = pd;
        }
    }
}

// ---------------- per-head global max of s_src (softmax stability bound) ---
__global__ void k_gmax_init() {
    if (threadIdx.x < 4) g_gmaxu[threadIdx.x] = 0u;  // < enc(any finite float)
}

__global__ void k_gmax() {
    float m0 = -1e30f, m1 = -1e30f, m2 = -1e30f, m3 = -1e30f;
    for (int v = blockIdx.x * blockDim.x + threadIdx.x; v < NN;
         v += gridDim.x * blockDim.x) {
        float4 s = ((const float4*)g_ssrc)[v];
        m0 = fmaxf(m0, s.x); m1 = fmaxf(m1, s.y);
        m2 = fmaxf(m2, s.z); m3 = fmaxf(m3, s.w);
    }
#pragma unroll
    for (int o = 16; o > 0; o >>= 1) {
        m0 = fmaxf(m0, __shfl_xor_sync(0xffffffffu, m0, o));
        m1 = fmaxf(m1, __shfl_xor_sync(0xffffffffu, m1, o));
        m2 = fmaxf(m2, __shfl_xor_sync(0xffffffffu, m2, o));
        m3 = fmaxf(m3, __shfl_xor_sync(0xffffffffu, m3, o));
    }
    __shared__ unsigned smx[4];
    if (threadIdx.x < 4) smx[threadIdx.x] = 0u;
    __syncthreads();
    if ((threadIdx.x & 31) == 0) {
        atomicMax(&smx[0], encf(m0));
        atomicMax(&smx[1], encf(m1));
        atomicMax(&smx[2], encf(m2));
        atomicMax(&smx[3], encf(m3));
    }
    __syncthreads();
    if (threadIdx.x < 4) atomicMax(&g_gmaxu[threadIdx.x], smx[threadIdx.x]);
}

// ---------------- warp-per-node single-pass softmax aggregation ------------
// mh = max(0, gmax_h + s_dst[v,h]) >= leaky(s_src[u]+s_dst[v]) for all u
// (leaky-relu monotone, <= max(0,x)); softmax is shift-invariant.
template <bool LAST>
__global__ void k_agg(const float* __restrict__ bias, float* __restrict__ outp) {
    int g = blockIdx.x * blockDim.x + threadIdx.x;
    int v = g >> 5, lane = g & 31;
    if (v >= NN) return;

    int offv = g_off[v];
    int deg = g_off[v + 1] - offv;

    int h2 = lane >> 3;
    float sd2 = g_sdst[v * 4 + h2];
    float mh = fmaxf(decf(g_gmaxu[h2]) + sd2, 0.f);

    float4 acc = make_float4(0.f, 0.f, 0.f, 0.f);
    float dsum = 0.f;

    int e = 0;
    for (; e + 2 <= deg; e += 2) {  // 2-way MLP on the gather chain
        int u0 = g_csr[offv + e];
        int u1 = g_csr[offv + e + 1];
        float a0 = g_ssrc[u0 * 4 + h2] + sd2;
        float a1 = g_ssrc[u1 * 4 + h2] + sd2;
        float4 x0 = ((const float4*)g_xw)[u0 * 32 + lane];
        float4 x1 = ((const float4*)g_xw)[u1 * 32 + lane];
        a0 = (a0 > 0.f) ? a0 : 0.2f * a0;
        a1 = (a1 > 0.f) ? a1 : 0.2f * a1;
        float e0 = __expf(a0 - mh);
        float e1 = __expf(a1 - mh);
        dsum += e0 + e1;
        acc.x += e0 * x0.x + e1 * x1.x;
        acc.y += e0 * x0.y + e1 * x1.y;
        acc.z += e0 * x0.z + e1 * x1.z;
        acc.w += e0 * x0.w + e1 * x1.w;
    }
    if (e < deg) {
        int u = g_csr[offv + e];
        float a = g_ssrc[u * 4 + h2] + sd2;
        float4 xu = ((const float4*)g_xw)[u * 32 + lane];
        a = (a > 0.f) ? a : 0.2f * a;
        float ex = __expf(a - mh);
        dsum += ex;
        acc.x += ex * xu.x;
        acc.y += ex * xu.y;
        acc.z += ex * xu.z;
        acc.w += ex * xu.w;
    }

    float inv = 1.f / dsum;
    acc.x *= inv; acc.y *= inv; acc.z *= inv; acc.w *= inv;

    if (!LAST) {
        float4 bv = ((const float4*)bias)[lane];
        float4 o;
        o.x = acc.x + bv.x; o.y = acc.y + bv.y;
        o.z = acc.z + bv.z; o.w = acc.w + bv.w;
        o.x = o.x > 0.f ? o.x : expm1f(o.x);
        o.y = o.y > 0.f ? o.y : expm1f(o.y);
        o.z = o.z > 0.f ? o.z : expm1f(o.z);
        o.w = o.w > 0.f ? o.w : expm1f(o.w);
        ((float4*)g_h)[v * 32 + lane] = o;
    } else {
        // mean over 4 heads: lanes {l, l+8, l+16, l+24} hold same within-head cols
        acc.x += __shfl_xor_sync(0xffffffffu, acc.x, 8);
        acc.y += __shfl_xor_sync(0xffffffffu, acc.y, 8);
        acc.z += __shfl_xor_sync(0xffffffffu, acc.z, 8);
        acc.w += __shfl_xor_sync(0xffffffffu, acc.w, 8);
        acc.x += __shfl_xor_sync(0xffffffffu, acc.x, 16);
        acc.y += __shfl_xor_sync(0xffffffffu, acc.y, 16);
        acc.z += __shfl_xor_sync(0xffffffffu, acc.z, 16);
        acc.w += __shfl_xor_sync(0xffffffffu, acc.w, 16);
        if (lane < 8) {
            float4 bv = ((const float4*)bias)[lane];
            float4 o = make_float4(acc.x * 0.25f + bv.x, acc.y * 0.25f + bv.y,
                                   acc.z * 0.25f + bv.z, acc.w * 0.25f + bv.w);
            ((float4*)outp)[v * 8 + lane] = o;
        }
    }
}

// ---------------- driver ----------------------------------------------------
extern "C" void kernel_launch(void* const* d_in, const int* in_sizes, int n_in,
                              void* d_out, int out_size) {
    const float* x   = (const float*)d_in[0];
    const int*   ei  = (const int*)d_in[1];
    const float* W1  = (const float*)d_in[2];
    const float* as1 = (const float*)d_in[3];
    const float* ad1 = (const float*)d_in[4];
    const float* b1  = (const float*)d_in[5];
    const float* W2  = (const float*)d_in[6];
    const float* as2 = (const float*)d_in[7];
    const float* ad2 = (const float*)d_in[8];
    const float* b2  = (const float*)d_in[9];
    const float* W3  = (const float*)d_in[10];
    const float* as3 = (const float*)d_in[11];
    const float* ad3 = (const float*)d_in[12];
    const float* b3  = (const float*)d_in[13];
    float* out = (float*)d_out;

    cudaFuncSetAttribute(k_gemm, cudaFuncAttributeMaxDynamicSharedMemorySize, 98304);

    // CSR by destination (g_cnt arrives zeroed: load-time init, then k_fill tail)
    k_count<<<(EE + 255) / 256, 256>>>(ei);      // launch 0
    k_scan1<<<98, 1024>>>();                     // launch 1
    k_scan2<<<1, 128>>>();                       // launch 2
    k_scan3<<<(NN + 255) / 256, 256>>>();        // launch 3
    k_fill<<<(ET + 255) / 256, 256>>>(ei);       // launch 4

    const int GB = (NN + 63) / 64;   // 1563
    const int WB = NN / 8;           // 12500 blocks, warp per node

    // layer 1  (k_gemm is launch 5 -> lands in the ncu -s 5 -c 1 window)
    k_gemm<<<GB, 256, 98304>>>(x, W1, as1, ad1, 0);
    k_gmax_init<<<1, 32>>>();
    k_gmax<<<160, 256>>>();
    k_agg<false><<<WB, 256>>>(b1, nullptr);
    // layer 2
    k_gemm<<<GB, 256, 98304>>>(nullptr, W2, as2, ad2, 1);
    k_gmax_init<<<1, 32>>>();
    k_gmax<<<160, 256>>>();
    k_agg<false><<<WB, 256>>>(b2, nullptr);
    // layer 3 (mean over heads)
    k_gemm<<<GB, 256, 98304>>>(nullptr, W3, as3, ad3, 1);
    k_gmax_init<<<1, 32>>>();
    k_gmax<<<160, 256>>>();
    k_agg<true><<<WB, 256>>>(b3, out);
}

// round 9
// speedup vs baseline: 1.8240x; 1.3248x over previous
#include <cuda_runtime.h>
#include <cuda_bf16.h>
#include <cstdint>

#define NN 100000
#define EE 1200000
#define ET (EE + NN)

// ---------------- scratch (static device memory: allocation-free) ----------
__device__ float g_xw[NN * 128];
__device__ float g_h[NN * 128];
__device__ float g_ssrc[NN * 4];
__device__ float g_sdst[NN * 4];
__device__ int   g_cnt[NN];        // zero at load; re-zeroed by k_fill tail
__device__ int   g_off[NN + 1];
__device__ int   g_cur[NN];
__device__ int   g_csr[ET];
__device__ int   g_bsum[128];
__device__ unsigned g_gmaxu[4];
// W images: transposed (B[n][k] = W[k][n]) bf16 hi/lo, padded rows of 272B
#define BSTRIDE 272
#define WIMG (128 * BSTRIDE)
__device__ __align__(16) unsigned char g_Wh[3][WIMG];
__device__ __align__(16) unsigned char g_Wl[3][WIMG];

// ---------------- small helpers ---------------------------------------------
__device__ __forceinline__ unsigned encf(float f) {
    unsigned u = __float_as_uint(f);
    return (u & 0x80000000u) ? ~u : (u | 0x80000000u);
}
__device__ __forceinline__ float decf(unsigned u) {
    return (u & 0x80000000u) ? __uint_as_float(u ^ 0x80000000u) : __uint_as_float(~u);
}
__device__ __forceinline__ uint32_t smem_u32(const void* p) {
    uint32_t a;
    asm("{ .reg .u64 t; cvta.to.shared.u64 t, %1; cvt.u32.u64 %0, t; }"
        : "=r"(a) : "l"(p));
    return a;
}
#define LDSM4(r, a) \
    asm volatile("ldmatrix.sync.aligned.m8n8.x4.shared.b16 {%0,%1,%2,%3},[%4];" \
        : "=r"((r)[0]), "=r"((r)[1]), "=r"((r)[2]), "=r"((r)[3]) : "r"(a))
#define LDSM2(r, a) \
    asm volatile("ldmatrix.sync.aligned.m8n8.x2.shared.b16 {%0,%1},[%2];" \
        : "=r"((r)[0]), "=r"((r)[1]) : "r"(a))
__device__ __forceinline__ void mma16816(float* c, const uint32_t* a, const uint32_t* b) {
    asm volatile(
        "mma.sync.aligned.m16n8k16.row.col.f32.bf16.bf16.f32 "
        "{%0,%1,%2,%3},{%4,%5,%6,%7},{%8,%9},{%0,%1,%2,%3};"
        : "+f"(c[0]), "+f"(c[1]), "+f"(c[2]), "+f"(c[3])
        : "r"(a[0]), "r"(a[1]), "r"(a[2]), "r"(a[3]), "r"(b[0]), "r"(b[1]));
}

// ---------------- CSR build -------------------------------------------------
__global__ void k_count(const int* __restrict__ ei) {
    int e = blockIdx.x * blockDim.x + threadIdx.x;
    if (e < EE) atomicAdd(&g_cnt[ei[EE + e]], 1);
}
__global__ void k_scan1() {
    __shared__ int s[1024];
    int i = blockIdx.x * 1024 + threadIdx.x;
    int v = (i < NN) ? g_cnt[i] : 0;
    s[threadIdx.x] = v;
    __syncthreads();
    for (int d = 1; d < 1024; d <<= 1) {
        int t = (threadIdx.x >= d) ? s[threadIdx.x - d] : 0;
        __syncthreads();
        s[threadIdx.x] += t;
        __syncthreads();
    }
    if (i < NN) g_off[i] = s[threadIdx.x] - v;
    if (threadIdx.x == 1023) g_bsum[blockIdx.x] = s[1023];
}
__global__ void k_scan2() {
    __shared__ int s[128];
    int v = (threadIdx.x < 98) ? g_bsum[threadIdx.x] : 0;
    s[threadIdx.x] = v;
    __syncthreads();
    for (int d = 1; d < 128; d <<= 1) {
        int t = (threadIdx.x >= d) ? s[threadIdx.x - d] : 0;
        __syncthreads();
        s[threadIdx.x] += t;
        __syncthreads();
    }
    g_bsum[threadIdx.x] = s[threadIdx.x] - v;
}
__global__ void k_scan3() {
    int i = blockIdx.x * blockDim.x + threadIdx.x;
    if (i < NN) {
        int o = g_off[i] + g_bsum[i >> 10] + i;  // +i folds self-loops
        g_off[i] = o;
        g_cur[i] = o;
    }
    if (i == 0) g_off[NN] = ET;
}
__global__ void k_fill(const int* __restrict__ ei) {
    int e = blockIdx.x * blockDim.x + threadIdx.x;
    if (e < EE) {
        int s = ei[e], d = ei[EE + e];
        g_csr[atomicAdd(&g_cur[d], 1)] = s;
    } else if (e < ET) {
        int v = e - EE;
        g_csr[atomicAdd(&g_cur[v], 1)] = v;
        g_cnt[v] = 0;
    }
}

// ---------------- W prep: transpose + bf16 hi/lo split ----------------------
__global__ void k_prep(const float* __restrict__ W1, const float* __restrict__ W2,
                       const float* __restrict__ W3) {
    int t = blockIdx.x * 256 + threadIdx.x;
    if (t >= 3 * 16384) return;
    int layer = t >> 14;
    int r = t & 16383;
    int n = r >> 7, k = r & 127;  // B[n][k] = W[k][n]
    const float* W = (layer == 0) ? W1 : (layer == 1) ? W2 : W3;
    float v = W[k * 128 + n];
    __nv_bfloat16 h = __float2bfloat16(v);
    __nv_bfloat16 l = __float2bfloat16(v - __bfloat162float(h));
    unsigned off = n * BSTRIDE + k * 2;
    *(__nv_bfloat16*)(g_Wh[layer] + off) = h;
    *(__nv_bfloat16*)(g_Wl[layer] + off) = l;
}

// ---------------- HMMA split-bf16 GEMM + fused scores + fused gmax ---------
#define OFF_BH 0
#define OFF_BL 34816
#define OFF_AH 69632
#define OFF_AL 104448
#define OFF_AS 139264
#define OFF_AD 139776
#define OFF_GM 140288
#define SMEM_TOT 140352

__global__ void __launch_bounds__(256, 1)
k_mm(const float* __restrict__ Xext,
     const float* __restrict__ asrc, const float* __restrict__ adst, int layer) {
    extern __shared__ __align__(16) unsigned char smem[];
    uint32_t sb = smem_u32(smem);
    int tid = threadIdx.x;
    int w = tid >> 5, lane = tid & 31;
    const float* X = layer ? (const float*)g_h : Xext;
    int row0 = blockIdx.x * 128;
    unsigned* sGM = (unsigned*)(smem + OFF_GM);

    if (tid < 4) sGM[tid] = 0u;
    // B images (hi+lo): plain 16B copies, 2176 uint4 each
    {
        const uint4* srcH = (const uint4*)g_Wh[layer];
        const uint4* srcL = (const uint4*)g_Wl[layer];
        uint4* dH = (uint4*)(smem + OFF_BH);
        uint4* dL = (uint4*)(smem + OFF_BL);
        for (int i = tid; i < 2176; i += 256) {
            dH[i] = srcH[i];
            dL[i] = srcL[i];
        }
    }
    if (tid < 128) {
        ((float*)(smem + OFF_AS))[tid] = asrc[tid];
        ((float*)(smem + OFF_AD))[tid] = adst[tid];
    }
    // A tile: fp32 -> bf16 hi/lo, padded rows (272B)
    for (int t = tid; t < 2048; t += 256) {
        int mrow = t >> 4, k0 = (t & 15) << 3;
        int gr = row0 + mrow;
        float4 v0 = make_float4(0.f, 0.f, 0.f, 0.f), v1 = v0;
        if (gr < NN) {
            v0 = ((const float4*)X)[gr * 32 + (k0 >> 2)];
            v1 = ((const float4*)X)[gr * 32 + (k0 >> 2) + 1];
        }
        float f[8] = {v0.x, v0.y, v0.z, v0.w, v1.x, v1.y, v1.z, v1.w};
        __nv_bfloat162 hi[4], lo[4];
#pragma unroll
        for (int j = 0; j < 4; j++) {
            __nv_bfloat16 h0 = __float2bfloat16(f[2 * j]);
            __nv_bfloat16 h1 = __float2bfloat16(f[2 * j + 1]);
            hi[j] = __nv_bfloat162(h0, h1);
            lo[j] = __nv_bfloat162(
                __float2bfloat16(f[2 * j] - __bfloat162float(h0)),
                __float2bfloat16(f[2 * j + 1] - __bfloat162float(h1)));
        }
        unsigned off = mrow * BSTRIDE + k0 * 2;
        *(uint4*)(smem + OFF_AH + off) = *(uint4*)hi;
        *(uint4*)(smem + OFF_AL + off) = *(uint4*)lo;
    }
    __syncthreads();

    // per-lane ldmatrix address offsets
    int lrow = lane & 7, lmat = lane >> 3;
    uint32_t aoff = (uint32_t)(((lmat & 1) * 8 + lrow) * BSTRIDE + (lmat >> 1) * 16);
    uint32_t boff = (uint32_t)((lane & 7) * BSTRIDE + ((lane >> 3) & 1) * 16);
    uint32_t aH = sb + OFF_AH + w * 16 * BSTRIDE + aoff;
    uint32_t aL = sb + OFF_AL + w * 16 * BSTRIDE + aoff;

    float acc[16][4];
#pragma unroll
    for (int nt = 0; nt < 16; nt++) {
        acc[nt][0] = 0.f; acc[nt][1] = 0.f; acc[nt][2] = 0.f; acc[nt][3] = 0.f;
    }

    // pass 1: (Ahi + Alo) x Bhi
#pragma unroll
    for (int s = 0; s < 8; s++) {
        uint32_t k2 = s * 32;
        uint32_t ah[4], al[4];
        LDSM4(ah, aH + k2);
        LDSM4(al, aL + k2);
        uint32_t bb = sb + OFF_BH + boff + k2;
#pragma unroll
        for (int nt = 0; nt < 16; nt++) {
            uint32_t bh[2];
            LDSM2(bh, bb + nt * (8 * BSTRIDE));
            mma16816(acc[nt], ah, bh);
            mma16816(acc[nt], al, bh);
        }
    }
    // pass 2: Ahi x Blo
#pragma unroll
    for (int s = 0; s < 8; s++) {
        uint32_t k2 = s * 32;
        uint32_t ah[4];
        LDSM4(ah, aH + k2);
        uint32_t bb = sb + OFF_BL + boff + k2;
#pragma unroll
        for (int nt = 0; nt < 16; nt++) {
            uint32_t bl[2];
            LDSM2(bl, bb + nt * (8 * BSTRIDE));
            mma16816(acc[nt], ah, bl);
        }
    }

    // epilogue: xw stores + per-head half-scores + block gmax
    const float* sAS = (const float*)(smem + OFF_AS);
    const float* sAD = (const float*)(smem + OFF_AD);
    int rbase = row0 + w * 16 + (lane >> 2);
#pragma unroll
    for (int rr = 0; rr < 2; rr++) {
        int m = rbase + rr * 8;
        float pss[4] = {0.f, 0.f, 0.f, 0.f};
        float pdd[4] = {0.f, 0.f, 0.f, 0.f};
#pragma unroll
        for (int nt = 0; nt < 16; nt++) {
            float c0 = acc[nt][rr * 2 + 0], c1 = acc[nt][rr * 2 + 1];
            int col = nt * 8 + (lane & 3) * 2;
            pss[nt >> 2] += c0 * sAS[col] + c1 * sAS[col + 1];
            pdd[nt >> 2] += c0 * sAD[col] + c1 * sAD[col + 1];
            if (m < NN) *(float2*)&g_xw[m * 128 + col] = make_float2(c0, c1);
        }
        float mysrc = 0.f, mydst = 0.f;
#pragma unroll
        for (int j = 0; j < 4; j++) {
            float t = pss[j];
            t += __shfl_xor_sync(0xffffffffu, t, 1);
            t += __shfl_xor_sync(0xffffffffu, t, 2);
            if ((lane & 3) == j) mysrc = t;
            t = pdd[j];
            t += __shfl_xor_sync(0xffffffffu, t, 1);
            t += __shfl_xor_sync(0xffffffffu, t, 2);
            if ((lane & 3) == j) mydst = t;
        }
        if (m < NN) {
            g_ssrc[m * 4 + (lane & 3)] = mysrc;
            g_sdst[m * 4 + (lane & 3)] = mydst;
            atomicMax(&sGM[lane & 3], encf(mysrc));
        }
    }
    __syncthreads();
    if (tid < 4) atomicMax(&g_gmaxu[tid], sGM[tid]);
}

// ---------------- gmax init --------------------------------------------------
__global__ void k_gmax_init() {
    if (threadIdx.x < 4) g_gmaxu[threadIdx.x] = 0u;
}

// ---------------- warp-per-node single-pass softmax aggregation ------------
// mh = max(0, gmax_h + s_dst[v,h]) >= leaky(s_src[u]+s_dst[v]); shift-invariant.
template <bool LAST>
__global__ void k_agg(const float* __restrict__ bias, float* __restrict__ outp) {
    int g = blockIdx.x * blockDim.x + threadIdx.x;
    int v = g >> 5, lane = g & 31;
    if (v >= NN) return;
    int offv = g_off[v];
    int deg = g_off[v + 1] - offv;
    int h2 = lane >> 3;
    float sd2 = g_sdst[v * 4 + h2];
    float mh = fmaxf(decf(g_gmaxu[h2]) + sd2, 0.f);

    float4 acc = make_float4(0.f, 0.f, 0.f, 0.f);
    float dsum = 0.f;
    int e = 0;
    for (; e + 2 <= deg; e += 2) {
        int u0 = g_csr[offv + e];
        int u1 = g_csr[offv + e + 1];
        float a0 = g_ssrc[u0 * 4 + h2] + sd2;
        float a1 = g_ssrc[u1 * 4 + h2] + sd2;
        float4 x0 = ((const float4*)g_xw)[u0 * 32 + lane];
        float4 x1 = ((const float4*)g_xw)[u1 * 32 + lane];
        a0 = (a0 > 0.f) ? a0 : 0.2f * a0;
        a1 = (a1 > 0.f) ? a1 : 0.2f * a1;
        float e0 = __expf(a0 - mh);
        float e1 = __expf(a1 - mh);
        dsum += e0 + e1;
        acc.x += e0 * x0.x + e1 * x1.x;
        acc.y += e0 * x0.y + e1 * x1.y;
        acc.z += e0 * x0.z + e1 * x1.z;
        acc.w += e0 * x0.w + e1 * x1.w;
    }
    if (e < deg) {
        int u = g_csr[offv + e];
        float a = g_ssrc[u * 4 + h2] + sd2;
        float4 xu = ((const float4*)g_xw)[u * 32 + lane];
        a = (a > 0.f) ? a : 0.2f * a;
        float ex = __expf(a - mh);
        dsum += ex;
        acc.x += ex * xu.x;
        acc.y += ex * xu.y;
        acc.z += ex * xu.z;
        acc.w += ex * xu.w;
    }
    float inv = 1.f / dsum;
    acc.x *= inv; acc.y *= inv; acc.z *= inv; acc.w *= inv;

    if (!LAST) {
        float4 bv = ((const float4*)bias)[lane];
        float4 o;
        o.x = acc.x + bv.x; o.y = acc.y + bv.y;
        o.z = acc.z + bv.z; o.w = acc.w + bv.w;
        o.x = o.x > 0.f ? o.x : expm1f(o.x);
        o.y = o.y > 0.f ? o.y : expm1f(o.y);
        o.z = o.z > 0.f ? o.z : expm1f(o.z);
        o.w = o.w > 0.f ? o.w : expm1f(o.w);
        ((float4*)g_h)[v * 32 + lane] = o;
    } else {
        acc.x += __shfl_xor_sync(0xffffffffu, acc.x, 8);
        acc.y += __shfl_xor_sync(0xffffffffu, acc.y, 8);
        acc.z += __shfl_xor_sync(0xffffffffu, acc.z, 8);
        acc.w += __shfl_xor_sync(0xffffffffu, acc.w, 8);
        acc.x += __shfl_xor_sync(0xffffffffu, acc.x, 16);
        acc.y += __shfl_xor_sync(0xffffffffu, acc.y, 16);
        acc.z += __shfl_xor_sync(0xffffffffu, acc.z, 16);
        acc.w += __shfl_xor_sync(0xffffffffu, acc.w, 16);
        if (lane < 8) {
            float4 bv = ((const float4*)bias)[lane];
            float4 o = make_float4(acc.x * 0.25f + bv.x, acc.y * 0.25f + bv.y,
                                   acc.z * 0.25f + bv.z, acc.w * 0.25f + bv.w);
            ((float4*)outp)[v * 8 + lane] = o;
        }
    }
}

// ---------------- driver ----------------------------------------------------
extern "C" void kernel_launch(void* const* d_in, const int* in_sizes, int n_in,
                              void* d_out, int out_size) {
    const float* x   = (const float*)d_in[0];
    const int*   ei  = (const int*)d_in[1];
    const float* W1  = (const float*)d_in[2];
    const float* as1 = (const float*)d_in[3];
    const float* ad1 = (const float*)d_in[4];
    const float* b1  = (const float*)d_in[5];
    const float* W2  = (const float*)d_in[6];
    const float* as2 = (const float*)d_in[7];
    const float* ad2 = (const float*)d_in[8];
    const float* b2  = (const float*)d_in[9];
    const float* W3  = (const float*)d_in[10];
    const float* as3 = (const float*)d_in[11];
    const float* ad3 = (const float*)d_in[12];
    const float* b3  = (const float*)d_in[13];
    float* out = (float*)d_out;

    cudaFuncSetAttribute(k_mm, cudaFuncAttributeMaxDynamicSharedMemorySize, SMEM_TOT);

    const int MB = (NN + 127) / 128;  // 782
    const int WB = NN / 8;            // 12500 blocks, warp per node

    // k_mm doesn't need the CSR; schedule so k_mm(L1) is launch #5 for ncu.
    k_prep<<<192, 256>>>(W1, W2, W3);            // 0
    k_gmax_init<<<1, 32>>>();                    // 1
    k_count<<<(EE + 255) / 256, 256>>>(ei);      // 2
    k_scan1<<<98, 1024>>>();                     // 3
    k_scan2<<<1, 128>>>();                       // 4
    k_mm<<<MB, 256, SMEM_TOT>>>(x, as1, ad1, 0); // 5  <- ncu -s 5 -c 1
    k_scan3<<<(NN + 255) / 256, 256>>>();        // 6
    k_fill<<<(ET + 255) / 256, 256>>>(ei);       // 7
    k_agg<false><<<WB, 256>>>(b1, nullptr);      // 8

    k_gmax_init<<<1, 32>>>();
    k_mm<<<MB, 256, SMEM_TOT>>>(nullptr, as2, ad2, 1);
    k_agg<false><<<WB, 256>>>(b2, nullptr);

    k_gmax_init<<<1, 32>>>();
    k_mm<<<MB, 256, SMEM_TOT>>>(nullptr, as3, ad3, 2);
    k_agg<true><<<WB, 256>>>(b3, out);
}

// round 11
// speedup vs baseline: 1.8814x; 1.0315x over previous
#include <cuda_runtime.h>
#include <cuda_bf16.h>
#include <cstdint>

#define NN 100000
#define EE 1200000
#define ET (EE + NN)

// ---------------- scratch (static device memory: allocation-free) ----------
__device__ float g_xw[NN * 128];
__device__ float g_h[NN * 128];
__device__ float g_ssrc[NN * 4];
__device__ float g_sdst[NN * 4];
__device__ int   g_cnt[NN];        // zero at load; re-zeroed by k_fill tail
__device__ int   g_off[NN + 1];
__device__ int   g_cur[NN];
__device__ int   g_csr[ET];
__device__ int   g_bsum[128];
__device__ unsigned g_gmaxu[3][4];   // per-layer slots, reset in k_prep
// W images: transposed (B[n][k] = W[k][n]) bf16 hi/lo, padded rows of 272B
#define BSTRIDE 272
#define WIMG (128 * BSTRIDE)
__device__ __align__(16) unsigned char g_Wh[3][WIMG];
__device__ __align__(16) unsigned char g_Wl[3][WIMG];

// ---------------- small helpers ---------------------------------------------
__device__ __forceinline__ unsigned encf(float f) {
    unsigned u = __float_as_uint(f);
    return (u & 0x80000000u) ? ~u : (u | 0x80000000u);
}
__device__ __forceinline__ float decf(unsigned u) {
    return (u & 0x80000000u) ? __uint_as_float(u ^ 0x80000000u) : __uint_as_float(~u);
}
__device__ __forceinline__ uint32_t smem_u32(const void* p) {
    uint32_t a;
    asm("{ .reg .u64 t; cvta.to.shared.u64 t, %1; cvt.u32.u64 %0, t; }"
        : "=r"(a) : "l"(p));
    return a;
}
#define LDSM4(r, a) \
    asm volatile("ldmatrix.sync.aligned.m8n8.x4.shared.b16 {%0,%1,%2,%3},[%4];" \
        : "=r"((r)[0]), "=r"((r)[1]), "=r"((r)[2]), "=r"((r)[3]) : "r"(a))
__device__ __forceinline__ void mma16816(float* c, const uint32_t* a, const uint32_t* b) {
    asm volatile(
        "mma.sync.aligned.m16n8k16.row.col.f32.bf16.bf16.f32 "
        "{%0,%1,%2,%3},{%4,%5,%6,%7},{%8,%9},{%0,%1,%2,%3};"
        : "+f"(c[0]), "+f"(c[1]), "+f"(c[2]), "+f"(c[3])
        : "r"(a[0]), "r"(a[1]), "r"(a[2]), "r"(a[3]), "r"(b[0]), "r"(b[1]));
}

// ---------------- CSR build -------------------------------------------------
__global__ void k_count(const int* __restrict__ ei) {
    int e = blockIdx.x * blockDim.x + threadIdx.x;
    if (e < EE) atomicAdd(&g_cnt[ei[EE + e]], 1);
}
__global__ void k_scan1() {
    __shared__ int s[1024];
    int i = blockIdx.x * 1024 + threadIdx.x;
    int v = (i < NN) ? g_cnt[i] : 0;
    s[threadIdx.x] = v;
    __syncthreads();
    for (int d = 1; d < 1024; d <<= 1) {
        int t = (threadIdx.x >= d) ? s[threadIdx.x - d] : 0;
        __syncthreads();
        s[threadIdx.x] += t;
        __syncthreads();
    }
    if (i < NN) g_off[i] = s[threadIdx.x] - v;
    if (threadIdx.x == 1023) g_bsum[blockIdx.x] = s[1023];
}
__global__ void k_scan2() {
    __shared__ int s[128];
    int v = (threadIdx.x < 98) ? g_bsum[threadIdx.x] : 0;
    s[threadIdx.x] = v;
    __syncthreads();
    for (int d = 1; d < 128; d <<= 1) {
        int t = (threadIdx.x >= d) ? s[threadIdx.x - d] : 0;
        __syncthreads();
        s[threadIdx.x] += t;
        __syncthreads();
    }
    g_bsum[threadIdx.x] = s[threadIdx.x] - v;
}
__global__ void k_scan3() {
    int i = blockIdx.x * blockDim.x + threadIdx.x;
    if (i < NN) {
        int o = g_off[i] + g_bsum[i >> 10] + i;  // +i folds self-loops
        g_off[i] = o;
        g_cur[i] = o;
    }
    if (i == 0) g_off[NN] = ET;
}
__global__ void k_fill(const int* __restrict__ ei) {
    int e = blockIdx.x * blockDim.x + threadIdx.x;
    if (e < EE) {
        int s = ei[e], d = ei[EE + e];
        g_csr[atomicAdd(&g_cur[d], 1)] = s;
    } else if (e < ET) {
        int v = e - EE;
        g_csr[atomicAdd(&g_cur[v], 1)] = v;
        g_cnt[v] = 0;
    }
}

// ---------------- W prep: transpose + bf16 hi/lo split + gmax reset --------
__global__ void k_prep(const float* __restrict__ W1, const float* __restrict__ W2,
                       const float* __restrict__ W3) {
    int t = blockIdx.x * 256 + threadIdx.x;
    if (t < 12) ((unsigned*)g_gmaxu)[t] = 0u;   // reset all per-layer gmax slots
    if (t >= 3 * 16384) return;
    int layer = t >> 14;
    int r = t & 16383;
    int n = r >> 7, k = r & 127;  // B[n][k] = W[k][n]
    const float* W = (layer == 0) ? W1 : (layer == 1) ? W2 : W3;
    float v = W[k * 128 + n];
    __nv_bfloat16 h = __float2bfloat16(v);
    __nv_bfloat16 l = __float2bfloat16(v - __bfloat162float(h));
    unsigned off = n * BSTRIDE + k * 2;
    *(__nv_bfloat16*)(g_Wh[layer] + off) = h;
    *(__nv_bfloat16*)(g_Wl[layer] + off) = l;
}

// ---------------- HMMA split-bf16 GEMM + fused scores + fused gmax ---------
#define OFF_BH 0
#define OFF_BL 34816
#define OFF_AH 69632
#define OFF_AL 104448
#define OFF_AS 139264
#define OFF_AD 139776
#define OFF_GM 140288
#define SMEM_TOT 140352

__global__ void __launch_bounds__(256, 1)
k_mm(const float* __restrict__ Xext,
     const float* __restrict__ asrc, const float* __restrict__ adst, int layer) {
    extern __shared__ __align__(16) unsigned char smem[];
    uint32_t sb = smem_u32(smem);
    int tid = threadIdx.x;
    int w = tid >> 5, lane = tid & 31;
    const float* X = layer ? (const float*)g_h : Xext;
    int row0 = blockIdx.x * 128;
    unsigned* sGM = (unsigned*)(smem + OFF_GM);

    if (tid < 4) sGM[tid] = 0u;
    // B images (hi+lo): plain 16B copies, 2176 uint4 each
    {
        const uint4* srcH = (const uint4*)g_Wh[layer];
        const uint4* srcL = (const uint4*)g_Wl[layer];
        uint4* dH = (uint4*)(smem + OFF_BH);
        uint4* dL = (uint4*)(smem + OFF_BL);
        for (int i = tid; i < 2176; i += 256) {
            dH[i] = srcH[i];
            dL[i] = srcL[i];
        }
    }
    if (tid < 128) {
        ((float*)(smem + OFF_AS))[tid] = asrc[tid];
        ((float*)(smem + OFF_AD))[tid] = adst[tid];
    }
    // A tile: fp32 -> bf16 hi/lo, padded rows (272B)
    for (int t = tid; t < 2048; t += 256) {
        int mrow = t >> 4, k0 = (t & 15) << 3;
        int gr = row0 + mrow;
        float4 v0 = make_float4(0.f, 0.f, 0.f, 0.f), v1 = v0;
        if (gr < NN) {
            v0 = ((const float4*)X)[gr * 32 + (k0 >> 2)];
            v1 = ((const float4*)X)[gr * 32 + (k0 >> 2) + 1];
        }
        float f[8] = {v0.x, v0.y, v0.z, v0.w, v1.x, v1.y, v1.z, v1.w};
        __nv_bfloat162 hi[4], lo[4];
#pragma unroll
        for (int j = 0; j < 4; j++) {
            __nv_bfloat16 h0 = __float2bfloat16(f[2 * j]);
            __nv_bfloat16 h1 = __float2bfloat16(f[2 * j + 1]);
            hi[j] = __nv_bfloat162(h0, h1);
            lo[j] = __nv_bfloat162(
                __float2bfloat16(f[2 * j] - __bfloat162float(h0)),
                __float2bfloat16(f[2 * j + 1] - __bfloat162float(h1)));
        }
        unsigned off = mrow * BSTRIDE + k0 * 2;
        *(uint4*)(smem + OFF_AH + off) = *(uint4*)hi;
        *(uint4*)(smem + OFF_AL + off) = *(uint4*)lo;
    }
    __syncthreads();

    // ldmatrix per-lane address offsets
    int lrow = lane & 7, lmat = lane >> 3;
    uint32_t aoff = (uint32_t)(((lmat & 1) * 8 + lrow) * BSTRIDE + (lmat >> 1) * 16);
    // B x4: lanes 0-7 -> (n row, k lo16B), 8-15 -> (n, k hi16B),
    //       16-23 -> (n+8, k lo), 24-31 -> (n+8, k hi)  => two n-tiles per LDSM4
    uint32_t boff = (uint32_t)(lrow * BSTRIDE + ((lane >> 3) & 1) * 16 +
                               (lane >> 4) * (8 * BSTRIDE));
    uint32_t aHa = sb + OFF_AH + w * 16 * BSTRIDE + aoff;
    uint32_t aLa = sb + OFF_AL + w * 16 * BSTRIDE + aoff;

    // hoist all A fragments (hi+lo) into registers: 16 LDSM4, 64 regs
    uint32_t ah[8][4], al[8][4];
#pragma unroll
    for (int s = 0; s < 8; s++) {
        LDSM4(ah[s], aHa + s * 32);
        LDSM4(al[s], aLa + s * 32);
    }

    float acc[16][4];
#pragma unroll
    for (int nt = 0; nt < 16; nt++) {
        acc[nt][0] = 0.f; acc[nt][1] = 0.f; acc[nt][2] = 0.f; acc[nt][3] = 0.f;
    }

    uint32_t bH = sb + OFF_BH + boff;
    uint32_t bL = sb + OFF_BL + boff;
#pragma unroll
    for (int p = 0; p < 8; p++) {           // n-tile pairs
        uint32_t ofs = p * (16 * BSTRIDE);
#pragma unroll
        for (int s = 0; s < 8; s++) {       // (Ahi + Alo) x Bhi
            uint32_t b4[4];
            LDSM4(b4, bH + ofs + s * 32);
            mma16816(acc[2 * p],     ah[s], b4);
            mma16816(acc[2 * p + 1], ah[s], b4 + 2);
            mma16816(acc[2 * p],     al[s], b4);
            mma16816(acc[2 * p + 1], al[s], b4 + 2);
        }
#pragma unroll
        for (int s = 0; s < 8; s++) {       // Ahi x Blo
            uint32_t b4[4];
            LDSM4(b4, bL + ofs + s * 32);
            mma16816(acc[2 * p],     ah[s], b4);
            mma16816(acc[2 * p + 1], ah[s], b4 + 2);
        }
    }

    // epilogue: xw stores + per-head half-scores + block gmax
    const float* sAS = (const float*)(smem + OFF_AS);
    const float* sAD = (const float*)(smem + OFF_AD);
    int rbase = row0 + w * 16 + (lane >> 2);
#pragma unroll
    for (int rr = 0; rr < 2; rr++) {
        int m = rbase + rr * 8;
        float pss[4] = {0.f, 0.f, 0.f, 0.f};
        float pdd[4] = {0.f, 0.f, 0.f, 0.f};
#pragma unroll
        for (int nt = 0; nt < 16; nt++) {
            float c0 = acc[nt][rr * 2 + 0], c1 = acc[nt][rr * 2 + 1];
            int col = nt * 8 + (lane & 3) * 2;
            pss[nt >> 2] += c0 * sAS[col] + c1 * sAS[col + 1];
            pdd[nt >> 2] += c0 * sAD[col] + c1 * sAD[col + 1];
            if (m < NN) *(float2*)&g_xw[m * 128 + col] = make_float2(c0, c1);
        }
        float mysrc = 0.f, mydst = 0.f;
#pragma unroll
        for (int j = 0; j < 4; j++) {
            float t = pss[j];
            t += __shfl_xor_sync(0xffffffffu, t, 1);
            t += __shfl_xor_sync(0xffffffffu, t, 2);
            if ((lane & 3) == j) mysrc = t;
            t = pdd[j];
            t += __shfl_xor_sync(0xffffffffu, t, 1);
            t += __shfl_xor_sync(0xffffffffu, t, 2);
            if ((lane & 3) == j) mydst = t;
        }
        if (m < NN) {
            g_ssrc[m * 4 + (lane & 3)] = mysrc;
            g_sdst[m * 4 + (lane & 3)] = mydst;
            atomicMax(&sGM[lane & 3], encf(mysrc));
        }
    }
    __syncthreads();
    if (tid < 4) atomicMax(&g_gmaxu[layer][tid], sGM[tid]);
}

// ---------------- warp-per-node single-pass softmax aggregation ------------
// mh = max(0, gmax_h + s_dst[v,h]) >= leaky(s_src[u]+s_dst[v]); shift-invariant.
template <bool LAST>
__global__ void k_agg(const float* __restrict__ bias, float* __restrict__ outp,
                      int layer) {
    int g = blockIdx.x * blockDim.x + threadIdx.x;
    int v = g >> 5, lane = g & 31;
    if (v >= NN) return;
    int offv = g_off[v];
    int deg = g_off[v + 1] - offv;
    int h2 = lane >> 3;
    float sd2 = g_sdst[v * 4 + h2];
    float mh = fmaxf(decf(g_gmaxu[layer][h2]) + sd2, 0.f);

    float4 acc = make_float4(0.f, 0.f, 0.f, 0.f);
    float dsum = 0.f;
    int e = 0;
    for (; e + 4 <= deg; e += 4) {
        int u0 = g_csr[offv + e];
        int u1 = g_csr[offv + e + 1];
        int u2 = g_csr[offv + e + 2];
        int u3 = g_csr[offv + e + 3];
        float a0 = g_ssrc[u0 * 4 + h2] + sd2;
        float a1 = g_ssrc[u1 * 4 + h2] + sd2;
        float a2 = g_ssrc[u2 * 4 + h2] + sd2;
        float a3 = g_ssrc[u3 * 4 + h2] + sd2;
        float4 x0 = ((const float4*)g_xw)[u0 * 32 + lane];
        float4 x1 = ((const float4*)g_xw)[u1 * 32 + lane];
        float4 x2 = ((const float4*)g_xw)[u2 * 32 + lane];
        float4 x3 = ((const float4*)g_xw)[u3 * 32 + lane];
        a0 = (a0 > 0.f) ? a0 : 0.2f * a0;
        a1 = (a1 > 0.f) ? a1 : 0.2f * a1;
        a2 = (a2 > 0.f) ? a2 : 0.2f * a2;
        a3 = (a3 > 0.f) ? a3 : 0.2f * a3;
        float e0 = __expf(a0 - mh);
        float e1 = __expf(a1 - mh);
        float e2 = __expf(a2 - mh);
        float e3 = __expf(a3 - mh);
        dsum += (e0 + e1) + (e2 + e3);
        acc.x += e0 * x0.x + e1 * x1.x + e2 * x2.x + e3 * x3.x;
        acc.y += e0 * x0.y + e1 * x1.y + e2 * x2.y + e3 * x3.y;
        acc.z += e0 * x0.z + e1 * x1.z + e2 * x2.z + e3 * x3.z;
        acc.w += e0 * x0.w + e1 * x1.w + e2 * x2.w + e3 * x3.w;
    }
    for (; e < deg; e++) {
        int u = g_csr[offv + e];
        float a = g_ssrc[u * 4 + h2] + sd2;
        float4 xu = ((const float4*)g_xw)[u * 32 + lane];
        a = (a > 0.f) ? a : 0.2f * a;
        float ex = __expf(a - mh);
        dsum += ex;
        acc.x += ex * xu.x;
        acc.y += ex * xu.y;
        acc.z += ex * xu.z;
        acc.w += ex * xu.w;
    }
    float inv = 1.f / dsum;
    acc.x *= inv; acc.y *= inv; acc.z *= inv; acc.w *= inv;

    if (!LAST) {
        float4 bv = ((const float4*)bias)[lane];
        float4 o;
        o.x = acc.x + bv.x; o.y = acc.y + bv.y;
        o.z = acc.z + bv.z; o.w = acc.w + bv.w;
        o.x = o.x > 0.f ? o.x : expm1f(o.x);
        o.y = o.y > 0.f ? o.y : expm1f(o.y);
        o.z = o.z > 0.f ? o.z : expm1f(o.z);
        o.w = o.w > 0.f ? o.w : expm1f(o.w);
        ((float4*)g_h)[v * 32 + lane] = o;
    } else {
        acc.x += __shfl_xor_sync(0xffffffffu, acc.x, 8);
        acc.y += __shfl_xor_sync(0xffffffffu, acc.y, 8);
        acc.z += __shfl_xor_sync(0xffffffffu, acc.z, 8);
        acc.w += __shfl_xor_sync(0xffffffffu, acc.w, 8);
        acc.x += __shfl_xor_sync(0xffffffffu, acc.x, 16);
        acc.y += __shfl_xor_sync(0xffffffffu, acc.y, 16);
        acc.z += __shfl_xor_sync(0xffffffffu, acc.z, 16);
        acc.w += __shfl_xor_sync(0xffffffffu, acc.w, 16);
        if (lane < 8) {
            float4 bv = ((const float4*)bias)[lane];
            float4 o = make_float4(acc.x * 0.25f + bv.x, acc.y * 0.25f + bv.y,
                                   acc.z * 0.25f + bv.z, acc.w * 0.25f + bv.w);
            ((float4*)outp)[v * 8 + lane] = o;
        }
    }
}

// ---------------- driver ----------------------------------------------------
extern "C" void kernel_launch(void* const* d_in, const int* in_sizes, int n_in,
                              void* d_out, int out_size) {
    const float* x   = (const float*)d_in[0];
    const int*   ei  = (const int*)d_in[1];
    const float* W1  = (const float*)d_in[2];
    const float* as1 = (const float*)d_in[3];
    const float* ad1 = (const float*)d_in[4];
    const float* b1  = (const float*)d_in[5];
    const float* W2  = (const float*)d_in[6];
    const float* as2 = (const float*)d_in[7];
    const float* ad2 = (const float*)d_in[8];
    const float* b2  = (const float*)d_in[9];
    const float* W3  = (const float*)d_in[10];
    const float* as3 = (const float*)d_in[11];
    const float* ad3 = (const float*)d_in[12];
    const float* b3  = (const float*)d_in[13];
    float* out = (float*)d_out;

    cudaFuncSetAttribute(k_mm, cudaFuncAttributeMaxDynamicSharedMemorySize, SMEM_TOT);

    const int MB = (NN + 127) / 128;  // 782
    const int WB = NN / 8;            // 12500 blocks, warp per node

    k_prep<<<192, 256>>>(W1, W2, W3);            // 0 (includes gmax reset)
    k_count<<<(EE + 255) / 256, 256>>>(ei);      // 1
    k_scan1<<<98, 1024>>>();                     // 2
    k_scan2<<<1, 128>>>();                       // 3
    k_scan3<<<(NN + 255) / 256, 256>>>();        // 4
    k_mm<<<MB, 256, SMEM_TOT>>>(x, as1, ad1, 0); // 5
    k_fill<<<(ET + 255) / 256, 256>>>(ei);       // 6
    k_agg<false><<<WB, 256>>>(b1, nullptr, 0);   // 7

    k_mm<<<MB, 256, SMEM_TOT>>>(nullptr, as2, ad2, 1);
    k_agg<false><<<WB, 256>>>(b2, nullptr, 1);

    k_mm<<<MB, 256, SMEM_TOT>>>(nullptr, as3, ad3, 2);
    k_agg<true><<<WB, 256>>>(b3, out, 2);
}

// round 12
// speedup vs baseline: 1.9636x; 1.0437x over previous
#include <cuda_runtime.h>
#include <cuda_bf16.h>
#include <cuda_fp16.h>
#include <cstdint>

#define NN 100000
#define EE 1200000
#define ET (EE + NN)

// ---------------- scratch (static device memory: allocation-free) ----------
__device__ __half g_xwh[NN * 128];   // post-GEMM features, fp16 (gather payload)
__device__ float g_h[NN * 128];      // aggregated layer output (GEMM input, fp32)
__device__ float g_ssrc[NN * 4];
__device__ float g_sdst[NN * 4];
__device__ int   g_cnt[NN];          // zero at load; re-zeroed by k_fill tail
__device__ int   g_off[NN + 1];
__device__ int   g_cur[NN];
__device__ int   g_csr[ET];
__device__ int   g_bsum[128];
__device__ unsigned g_gmaxu[3][4];   // per-layer slots, reset in k_prep
// W images: transposed (B[n][k] = W[k][n]) bf16 hi/lo, padded rows of 272B
#define BSTRIDE 272
#define WIMG (128 * BSTRIDE)
__device__ __align__(16) unsigned char g_Wh[3][WIMG];
__device__ __align__(16) unsigned char g_Wl[3][WIMG];

// ---------------- small helpers ---------------------------------------------
__device__ __forceinline__ unsigned encf(float f) {
    unsigned u = __float_as_uint(f);
    return (u & 0x80000000u) ? ~u : (u | 0x80000000u);
}
__device__ __forceinline__ float decf(unsigned u) {
    return (u & 0x80000000u) ? __uint_as_float(u ^ 0x80000000u) : __uint_as_float(~u);
}
__device__ __forceinline__ uint32_t smem_u32(const void* p) {
    uint32_t a;
    asm("{ .reg .u64 t; cvta.to.shared.u64 t, %1; cvt.u32.u64 %0, t; }"
        : "=r"(a) : "l"(p));
    return a;
}
#define LDSM4(r, a) \
    asm volatile("ldmatrix.sync.aligned.m8n8.x4.shared.b16 {%0,%1,%2,%3},[%4];" \
        : "=r"((r)[0]), "=r"((r)[1]), "=r"((r)[2]), "=r"((r)[3]) : "r"(a))
__device__ __forceinline__ void mma16816(float* c, const uint32_t* a, const uint32_t* b) {
    asm volatile(
        "mma.sync.aligned.m16n8k16.row.col.f32.bf16.bf16.f32 "
        "{%0,%1,%2,%3},{%4,%5,%6,%7},{%8,%9},{%0,%1,%2,%3};"
        : "+f"(c[0]), "+f"(c[1]), "+f"(c[2]), "+f"(c[3])
        : "r"(a[0]), "r"(a[1]), "r"(a[2]), "r"(a[3]), "r"(b[0]), "r"(b[1]));
}
// unpack uint2 holding 4 halves -> 4 floats
__device__ __forceinline__ void up4h(uint2 q, float& x, float& y, float& z, float& w) {
    float2 a = __half22float2(*(__half2*)&q.x);
    float2 b = __half22float2(*(__half2*)&q.y);
    x = a.x; y = a.y; z = b.x; w = b.y;
}

// ---------------- CSR build -------------------------------------------------
__global__ void k_count(const int* __restrict__ ei) {
    int e = blockIdx.x * blockDim.x + threadIdx.x;
    if (e < EE) atomicAdd(&g_cnt[ei[EE + e]], 1);
}
__global__ void k_scan1() {
    __shared__ int s[1024];
    int i = blockIdx.x * 1024 + threadIdx.x;
    int v = (i < NN) ? g_cnt[i] : 0;
    s[threadIdx.x] = v;
    __syncthreads();
    for (int d = 1; d < 1024; d <<= 1) {
        int t = (threadIdx.x >= d) ? s[threadIdx.x - d] : 0;
        __syncthreads();
        s[threadIdx.x] += t;
        __syncthreads();
    }
    if (i < NN) g_off[i] = s[threadIdx.x] - v;
    if (threadIdx.x == 1023) g_bsum[blockIdx.x] = s[1023];
}
__global__ void k_scan2() {
    __shared__ int s[128];
    int v = (threadIdx.x < 98) ? g_bsum[threadIdx.x] : 0;
    s[threadIdx.x] = v;
    __syncthreads();
    for (int d = 1; d < 128; d <<= 1) {
        int t = (threadIdx.x >= d) ? s[threadIdx.x - d] : 0;
        __syncthreads();
        s[threadIdx.x] += t;
        __syncthreads();
    }
    g_bsum[threadIdx.x] = s[threadIdx.x] - v;
}
__global__ void k_scan3() {
    int i = blockIdx.x * blockDim.x + threadIdx.x;
    if (i < NN) {
        int o = g_off[i] + g_bsum[i >> 10] + i;  // +i folds self-loops
        g_off[i] = o;
        g_cur[i] = o;
    }
    if (i == 0) g_off[NN] = ET;
}
__global__ void k_fill(const int* __restrict__ ei) {
    int e = blockIdx.x * blockDim.x + threadIdx.x;
    if (e < EE) {
        int s = ei[e], d = ei[EE + e];
        g_csr[atomicAdd(&g_cur[d], 1)] = s;
    } else if (e < ET) {
        int v = e - EE;
        g_csr[atomicAdd(&g_cur[v], 1)] = v;
        g_cnt[v] = 0;
    }
}

// ---------------- W prep: transpose + bf16 hi/lo split + gmax reset --------
__global__ void k_prep(const float* __restrict__ W1, const float* __restrict__ W2,
                       const float* __restrict__ W3) {
    int t = blockIdx.x * 256 + threadIdx.x;
    if (t < 12) ((unsigned*)g_gmaxu)[t] = 0u;
    if (t >= 3 * 16384) return;
    int layer = t >> 14;
    int r = t & 16383;
    int n = r >> 7, k = r & 127;  // B[n][k] = W[k][n]
    const float* W = (layer == 0) ? W1 : (layer == 1) ? W2 : W3;
    float v = W[k * 128 + n];
    __nv_bfloat16 h = __float2bfloat16(v);
    __nv_bfloat16 l = __float2bfloat16(v - __bfloat162float(h));
    unsigned off = n * BSTRIDE + k * 2;
    *(__nv_bfloat16*)(g_Wh[layer] + off) = h;
    *(__nv_bfloat16*)(g_Wl[layer] + off) = l;
}

// ---------------- HMMA split-bf16 GEMM + fused scores + fused gmax ---------
#define OFF_BH 0
#define OFF_BL 34816
#define OFF_AH 69632
#define OFF_AL 104448
#define OFF_AS 139264
#define OFF_AD 139776
#define OFF_GM 140288
#define SMEM_TOT 140352

__global__ void __launch_bounds__(256, 1)
k_mm(const float* __restrict__ Xext,
     const float* __restrict__ asrc, const float* __restrict__ adst, int layer) {
    extern __shared__ __align__(16) unsigned char smem[];
    uint32_t sb = smem_u32(smem);
    int tid = threadIdx.x;
    int w = tid >> 5, lane = tid & 31;
    const float* X = layer ? (const float*)g_h : Xext;
    int row0 = blockIdx.x * 128;
    unsigned* sGM = (unsigned*)(smem + OFF_GM);

    if (tid < 4) sGM[tid] = 0u;
    {
        const uint4* srcH = (const uint4*)g_Wh[layer];
        const uint4* srcL = (const uint4*)g_Wl[layer];
        uint4* dH = (uint4*)(smem + OFF_BH);
        uint4* dL = (uint4*)(smem + OFF_BL);
        for (int i = tid; i < 2176; i += 256) {
            dH[i] = srcH[i];
            dL[i] = srcL[i];
        }
    }
    if (tid < 128) {
        ((float*)(smem + OFF_AS))[tid] = asrc[tid];
        ((float*)(smem + OFF_AD))[tid] = adst[tid];
    }
    // A tile: fp32 -> bf16 hi/lo, padded rows (272B)
    for (int t = tid; t < 2048; t += 256) {
        int mrow = t >> 4, k0 = (t & 15) << 3;
        int gr = row0 + mrow;
        float4 v0 = make_float4(0.f, 0.f, 0.f, 0.f), v1 = v0;
        if (gr < NN) {
            v0 = ((const float4*)X)[gr * 32 + (k0 >> 2)];
            v1 = ((const float4*)X)[gr * 32 + (k0 >> 2) + 1];
        }
        float f[8] = {v0.x, v0.y, v0.z, v0.w, v1.x, v1.y, v1.z, v1.w};
        __nv_bfloat162 hi[4], lo[4];
#pragma unroll
        for (int j = 0; j < 4; j++) {
            __nv_bfloat16 h0 = __float2bfloat16(f[2 * j]);
            __nv_bfloat16 h1 = __float2bfloat16(f[2 * j + 1]);
            hi[j] = __nv_bfloat162(h0, h1);
            lo[j] = __nv_bfloat162(
                __float2bfloat16(f[2 * j] - __bfloat162float(h0)),
                __float2bfloat16(f[2 * j + 1] - __bfloat162float(h1)));
        }
        unsigned off = mrow * BSTRIDE + k0 * 2;
        *(uint4*)(smem + OFF_AH + off) = *(uint4*)hi;
        *(uint4*)(smem + OFF_AL + off) = *(uint4*)lo;
    }
    __syncthreads();

    int lrow = lane & 7, lmat = lane >> 3;
    uint32_t aoff = (uint32_t)(((lmat & 1) * 8 + lrow) * BSTRIDE + (lmat >> 1) * 16);
    uint32_t boff = (uint32_t)(lrow * BSTRIDE + ((lane >> 3) & 1) * 16 +
                               (lane >> 4) * (8 * BSTRIDE));
    uint32_t aHa = sb + OFF_AH + w * 16 * BSTRIDE + aoff;
    uint32_t aLa = sb + OFF_AL + w * 16 * BSTRIDE + aoff;

    uint32_t ah[8][4], al[8][4];
#pragma unroll
    for (int s = 0; s < 8; s++) {
        LDSM4(ah[s], aHa + s * 32);
        LDSM4(al[s], aLa + s * 32);
    }

    float acc[16][4];
#pragma unroll
    for (int nt = 0; nt < 16; nt++) {
        acc[nt][0] = 0.f; acc[nt][1] = 0.f; acc[nt][2] = 0.f; acc[nt][3] = 0.f;
    }

    uint32_t bH = sb + OFF_BH + boff;
    uint32_t bL = sb + OFF_BL + boff;
#pragma unroll
    for (int p = 0; p < 8; p++) {
        uint32_t ofs = p * (16 * BSTRIDE);
#pragma unroll
        for (int s = 0; s < 8; s++) {
            uint32_t b4[4];
            LDSM4(b4, bH + ofs + s * 32);
            mma16816(acc[2 * p],     ah[s], b4);
            mma16816(acc[2 * p + 1], ah[s], b4 + 2);
            mma16816(acc[2 * p],     al[s], b4);
            mma16816(acc[2 * p + 1], al[s], b4 + 2);
        }
#pragma unroll
        for (int s = 0; s < 8; s++) {
            uint32_t b4[4];
            LDSM4(b4, bL + ofs + s * 32);
            mma16816(acc[2 * p],     ah[s], b4);
            mma16816(acc[2 * p + 1], ah[s], b4 + 2);
        }
    }

    // epilogue: fp16 xw stores + per-head half-scores + block gmax
    const float* sAS = (const float*)(smem + OFF_AS);
    const float* sAD = (const float*)(smem + OFF_AD);
    int rbase = row0 + w * 16 + (lane >> 2);
#pragma unroll
    for (int rr = 0; rr < 2; rr++) {
        int m = rbase + rr * 8;
        float pss[4] = {0.f, 0.f, 0.f, 0.f};
        float pdd[4] = {0.f, 0.f, 0.f, 0.f};
#pragma unroll
        for (int nt = 0; nt < 16; nt++) {
            float c0 = acc[nt][rr * 2 + 0], c1 = acc[nt][rr * 2 + 1];
            int col = nt * 8 + (lane & 3) * 2;
            pss[nt >> 2] += c0 * sAS[col] + c1 * sAS[col + 1];
            pdd[nt >> 2] += c0 * sAD[col] + c1 * sAD[col + 1];
            if (m < NN) {
                __half2 hp = __floats2half2_rn(c0, c1);
                *(unsigned*)&g_xwh[m * 128 + col] = *(unsigned*)&hp;
            }
        }
        float mysrc = 0.f, mydst = 0.f;
#pragma unroll
        for (int j = 0; j < 4; j++) {
            float t = pss[j];
            t += __shfl_xor_sync(0xffffffffu, t, 1);
            t += __shfl_xor_sync(0xffffffffu, t, 2);
            if ((lane & 3) == j) mysrc = t;
            t = pdd[j];
            t += __shfl_xor_sync(0xffffffffu, t, 1);
            t += __shfl_xor_sync(0xffffffffu, t, 2);
            if ((lane & 3) == j) mydst = t;
        }
        if (m < NN) {
            g_ssrc[m * 4 + (lane & 3)] = mysrc;
            g_sdst[m * 4 + (lane & 3)] = mydst;
            atomicMax(&sGM[lane & 3], encf(mysrc));
        }
    }
    __syncthreads();
    if (tid < 4) atomicMax(&g_gmaxu[layer][tid], sGM[tid]);
}

// ---------------- warp-per-node single-pass softmax aggregation ------------
// mh = max(0, gmax_h + s_dst[v,h]) >= leaky(s_src[u]+s_dst[v]); shift-invariant.
template <bool LAST>
__global__ void k_agg(const float* __restrict__ bias, float* __restrict__ outp,
                      int layer) {
    int g = blockIdx.x * blockDim.x + threadIdx.x;
    int v = g >> 5, lane = g & 31;
    if (v >= NN) return;
    int offv = g_off[v];
    int deg = g_off[v + 1] - offv;
    int h2 = lane >> 3;
    float sd2 = g_sdst[v * 4 + h2];
    float mh = fmaxf(decf(g_gmaxu[layer][h2]) + sd2, 0.f);

    const uint2* XW = (const uint2*)g_xwh;  // 4 halves per lane-slot

    float4 acc = make_float4(0.f, 0.f, 0.f, 0.f);
    float dsum = 0.f;
    int e = 0;
    for (; e + 4 <= deg; e += 4) {
        int u0 = g_csr[offv + e];
        int u1 = g_csr[offv + e + 1];
        int u2 = g_csr[offv + e + 2];
        int u3 = g_csr[offv + e + 3];
        float a0 = g_ssrc[u0 * 4 + h2] + sd2;
        float a1 = g_ssrc[u1 * 4 + h2] + sd2;
        float a2 = g_ssrc[u2 * 4 + h2] + sd2;
        float a3 = g_ssrc[u3 * 4 + h2] + sd2;
        uint2 q0 = XW[u0 * 32 + lane];
        uint2 q1 = XW[u1 * 32 + lane];
        uint2 q2 = XW[u2 * 32 + lane];
        uint2 q3 = XW[u3 * 32 + lane];
        a0 = (a0 > 0.f) ? a0 : 0.2f * a0;
        a1 = (a1 > 0.f) ? a1 : 0.2f * a1;
        a2 = (a2 > 0.f) ? a2 : 0.2f * a2;
        a3 = (a3 > 0.f) ? a3 : 0.2f * a3;
        float e0 = __expf(a0 - mh);
        float e1 = __expf(a1 - mh);
        float e2 = __expf(a2 - mh);
        float e3 = __expf(a3 - mh);
        dsum += (e0 + e1) + (e2 + e3);
        float x0, y0, z0, w0, x1, y1, z1, w1;
        float x2, y2, z2, w2, x3, y3, z3, w3;
        up4h(q0, x0, y0, z0, w0);
        up4h(q1, x1, y1, z1, w1);
        up4h(q2, x2, y2, z2, w2);
        up4h(q3, x3, y3, z3, w3);
        acc.x += e0 * x0 + e1 * x1 + e2 * x2 + e3 * x3;
        acc.y += e0 * y0 + e1 * y1 + e2 * y2 + e3 * y3;
        acc.z += e0 * z0 + e1 * z1 + e2 * z2 + e3 * z3;
        acc.w += e0 * w0 + e1 * w1 + e2 * w2 + e3 * w3;
    }
    for (; e < deg; e++) {
        int u = g_csr[offv + e];
        float a = g_ssrc[u * 4 + h2] + sd2;
        uint2 q = XW[u * 32 + lane];
        a = (a > 0.f) ? a : 0.2f * a;
        float ex = __expf(a - mh);
        dsum += ex;
        float x, y, z, wv;
        up4h(q, x, y, z, wv);
        acc.x += ex * x;
        acc.y += ex * y;
        acc.z += ex * z;
        acc.w += ex * wv;
    }
    float inv = 1.f / dsum;
    acc.x *= inv; acc.y *= inv; acc.z *= inv; acc.w *= inv;

    if (!LAST) {
        float4 bv = ((const float4*)bias)[lane];
        float4 o;
        o.x = acc.x + bv.x; o.y = acc.y + bv.y;
        o.z = acc.z + bv.z; o.w = acc.w + bv.w;
        o.x = o.x > 0.f ? o.x : expm1f(o.x);
        o.y = o.y > 0.f ? o.y : expm1f(o.y);
        o.z = o.z > 0.f ? o.z : expm1f(o.z);
        o.w = o.w > 0.f ? o.w : expm1f(o.w);
        ((float4*)g_h)[v * 32 + lane] = o;
    } else {
        acc.x += __shfl_xor_sync(0xffffffffu, acc.x, 8);
        acc.y += __shfl_xor_sync(0xffffffffu, acc.y, 8);
        acc.z += __shfl_xor_sync(0xffffffffu, acc.z, 8);
        acc.w += __shfl_xor_sync(0xffffffffu, acc.w, 8);
        acc.x += __shfl_xor_sync(0xffffffffu, acc.x, 16);
        acc.y += __shfl_xor_sync(0xffffffffu, acc.y, 16);
        acc.z += __shfl_xor_sync(0xffffffffu, acc.z, 16);
        acc.w += __shfl_xor_sync(0xffffffffu, acc.w, 16);
        if (lane < 8) {
            float4 bv = ((const float4*)bias)[lane];
            float4 o = make_float4(acc.x * 0.25f + bv.x, acc.y * 0.25f + bv.y,
                                   acc.z * 0.25f + bv.z, acc.w * 0.25f + bv.w);
            ((float4*)outp)[v * 8 + lane] = o;
        }
    }
}

// ---------------- driver ----------------------------------------------------
extern "C" void kernel_launch(void* const* d_in, const int* in_sizes, int n_in,
                              void* d_out, int out_size) {
    const float* x   = (const float*)d_in[0];
    const int*   ei  = (const int*)d_in[1];
    const float* W1  = (const float*)d_in[2];
    const float* as1 = (const float*)d_in[3];
    const float* ad1 = (const float*)d_in[4];
    const float* b1  = (const float*)d_in[5];
    const float* W2  = (const float*)d_in[6];
    const float* as2 = (const float*)d_in[7];
    const float* ad2 = (const float*)d_in[8];
    const float* b2  = (const float*)d_in[9];
    const float* W3  = (const float*)d_in[10];
    const float* as3 = (const float*)d_in[11];
    const float* ad3 = (const float*)d_in[12];
    const float* b3  = (const float*)d_in[13];
    float* out = (float*)d_out;

    cudaFuncSetAttribute(k_mm, cudaFuncAttributeMaxDynamicSharedMemorySize, SMEM_TOT);

    const int MB = (NN + 127) / 128;  // 782
    const int WB = NN / 8;            // 12500 blocks, warp per node

    k_prep<<<192, 256>>>(W1, W2, W3);            // 0 (includes gmax reset)
    k_count<<<(EE + 255) / 256, 256>>>(ei);      // 1
    k_scan1<<<98, 1024>>>();                     // 2
    k_scan2<<<1, 128>>>();                       // 3
    k_scan3<<<(NN + 255) / 256, 256>>>();        // 4
    k_mm<<<MB, 256, SMEM_TOT>>>(x, as1, ad1, 0); // 5
    k_fill<<<(ET + 255) / 256, 256>>>(ei);       // 6
    k_agg<false><<<WB, 256>>>(b1, nullptr, 0);   // 7

    k_mm<<<MB, 256, SMEM_TOT>>>(nullptr, as2, ad2, 1);
    k_agg<false><<<WB, 256>>>(b2, nullptr, 1);

    k_mm<<<MB, 256, SMEM_TOT>>>(nullptr, as3, ad3, 2);
    k_agg<true><<<WB, 256>>>(b3, out, 2);
}

// round 13
// speedup vs baseline: 2.0854x; 1.0620x over previous
#include <cuda_runtime.h>
#include <cuda_bf16.h>
#include <cuda_fp16.h>
#include <cstdint>

#define NN 100000
#define EE 1200000
#define ET (EE + NN)

// ---------------- scratch (static device memory: allocation-free) ----------
__device__ __half g_xwh[NN * 128];   // post-GEMM features, fp16 (gather payload)
__device__ float g_h[NN * 128];      // aggregated layer output (GEMM input, fp32)
__device__ float g_ssrc[NN * 4];
__device__ float g_sdst[NN * 4];
__device__ int   g_cnt[NN];          // zero at load; re-zeroed by k_fill tail
__device__ int   g_off[NN + 1];
__device__ int   g_rank[EE];         // within-node edge rank (from k_count)
__device__ int   g_csr[ET];
__device__ int   g_bsum[128];
__device__ unsigned g_gmaxu[3][4];   // per-layer slots, reset in k_prep
// W images: transposed (B[n][k] = W[k][n]) bf16 hi/lo, padded rows of 272B
#define BSTRIDE 272
#define WIMG (128 * BSTRIDE)
__device__ __align__(16) unsigned char g_Wh[3][WIMG];
__device__ __align__(16) unsigned char g_Wl[3][WIMG];

// ---------------- small helpers ---------------------------------------------
__device__ __forceinline__ unsigned encf(float f) {
    unsigned u = __float_as_uint(f);
    return (u & 0x80000000u) ? ~u : (u | 0x80000000u);
}
__device__ __forceinline__ float decf(unsigned u) {
    return (u & 0x80000000u) ? __uint_as_float(u ^ 0x80000000u) : __uint_as_float(~u);
}
__device__ __forceinline__ uint32_t smem_u32(const void* p) {
    uint32_t a;
    asm("{ .reg .u64 t; cvta.to.shared.u64 t, %1; cvt.u32.u64 %0, t; }"
        : "=r"(a) : "l"(p));
    return a;
}
#define LDSM4(r, a) \
    asm volatile("ldmatrix.sync.aligned.m8n8.x4.shared.b16 {%0,%1,%2,%3},[%4];" \
        : "=r"((r)[0]), "=r"((r)[1]), "=r"((r)[2]), "=r"((r)[3]) : "r"(a))
__device__ __forceinline__ void mma16816(float* c, const uint32_t* a, const uint32_t* b) {
    asm volatile(
        "mma.sync.aligned.m16n8k16.row.col.f32.bf16.bf16.f32 "
        "{%0,%1,%2,%3},{%4,%5,%6,%7},{%8,%9},{%0,%1,%2,%3};"
        : "+f"(c[0]), "+f"(c[1]), "+f"(c[2]), "+f"(c[3])
        : "r"(a[0]), "r"(a[1]), "r"(a[2]), "r"(a[3]), "r"(b[0]), "r"(b[1]));
}
__device__ __forceinline__ void up4h(uint2 q, float& x, float& y, float& z, float& w) {
    float2 a = __half22float2(*(__half2*)&q.x);
    float2 b = __half22float2(*(__half2*)&q.y);
    x = a.x; y = a.y; z = b.x; w = b.y;
}

// ---------------- CSR build -------------------------------------------------
__global__ void k_count(const int* __restrict__ ei) {
    int e = blockIdx.x * blockDim.x + threadIdx.x;
    if (e < EE) g_rank[e] = atomicAdd(&g_cnt[ei[EE + e]], 1);
}
__global__ void k_scan1() {
    __shared__ int s[1024];
    int i = blockIdx.x * 1024 + threadIdx.x;
    int v = (i < NN) ? g_cnt[i] : 0;
    s[threadIdx.x] = v;
    __syncthreads();
    for (int d = 1; d < 1024; d <<= 1) {
        int t = (threadIdx.x >= d) ? s[threadIdx.x - d] : 0;
        __syncthreads();
        s[threadIdx.x] += t;
        __syncthreads();
    }
    if (i < NN) g_off[i] = s[threadIdx.x] - v;
    if (threadIdx.x == 1023) g_bsum[blockIdx.x] = s[1023];
}
__global__ void k_scan2() {
    __shared__ int s[128];
    int v = (threadIdx.x < 98) ? g_bsum[threadIdx.x] : 0;
    s[threadIdx.x] = v;
    __syncthreads();
    for (int d = 1; d < 128; d <<= 1) {
        int t = (threadIdx.x >= d) ? s[threadIdx.x - d] : 0;
        __syncthreads();
        s[threadIdx.x] += t;
        __syncthreads();
    }
    g_bsum[threadIdx.x] = s[threadIdx.x] - v;
}
__global__ void k_scan3() {
    int i = blockIdx.x * blockDim.x + threadIdx.x;
    if (i < NN) g_off[i] = g_off[i] + g_bsum[i >> 10] + i;  // +i folds self-loops
    if (i == 0) g_off[NN] = ET;
}
__global__ void k_fill(const int* __restrict__ ei) {
    int e = blockIdx.x * blockDim.x + threadIdx.x;
    if (e < EE) {
        int d = ei[EE + e];
        g_csr[g_off[d] + g_rank[e]] = ei[e];   // atomic-free via precomputed rank
    } else if (e < ET) {
        int v = e - EE;
        g_csr[g_off[v + 1] - 1] = v;           // self-loop in the last slot
        g_cnt[v] = 0;                          // reset for next call
    }
}

// ---------------- W prep: transpose + bf16 hi/lo split + gmax reset --------
__global__ void k_prep(const float* __restrict__ W1, const float* __restrict__ W2,
                       const float* __restrict__ W3) {
    int t = blockIdx.x * 256 + threadIdx.x;
    if (t < 12) ((unsigned*)g_gmaxu)[t] = 0u;
    if (t >= 3 * 16384) return;
    int layer = t >> 14;
    int r = t & 16383;
    int n = r >> 7, k = r & 127;  // B[n][k] = W[k][n]
    const float* W = (layer == 0) ? W1 : (layer == 1) ? W2 : W3;
    float v = W[k * 128 + n];
    __nv_bfloat16 h = __float2bfloat16(v);
    __nv_bfloat16 l = __float2bfloat16(v - __bfloat162float(h));
    unsigned off = n * BSTRIDE + k * 2;
    *(__nv_bfloat16*)(g_Wh[layer] + off) = h;
    *(__nv_bfloat16*)(g_Wl[layer] + off) = l;
}

// ---------------- HMMA split-bf16 GEMM + fused scores + fused gmax ---------
#define OFF_BH 0
#define OFF_BL 34816
#define OFF_AH 69632
#define OFF_AL 104448
#define OFF_AS 139264
#define OFF_AD 139776
#define OFF_GM 140288
#define SMEM_TOT 140352

__global__ void __launch_bounds__(256, 1)
k_mm(const float* __restrict__ Xext,
     const float* __restrict__ asrc, const float* __restrict__ adst, int layer) {
    extern __shared__ __align__(16) unsigned char smem[];
    uint32_t sb = smem_u32(smem);
    int tid = threadIdx.x;
    int w = tid >> 5, lane = tid & 31;
    const float* X = layer ? (const float*)g_h : Xext;
    int row0 = blockIdx.x * 128;
    unsigned* sGM = (unsigned*)(smem + OFF_GM);

    if (tid < 4) sGM[tid] = 0u;
    {
        const uint4* srcH = (const uint4*)g_Wh[layer];
        const uint4* srcL = (const uint4*)g_Wl[layer];
        uint4* dH = (uint4*)(smem + OFF_BH);
        uint4* dL = (uint4*)(smem + OFF_BL);
        for (int i = tid; i < 2176; i += 256) {
            dH[i] = srcH[i];
            dL[i] = srcL[i];
        }
    }
    if (tid < 128) {
        ((float*)(smem + OFF_AS))[tid] = asrc[tid];
        ((float*)(smem + OFF_AD))[tid] = adst[tid];
    }
    for (int t = tid; t < 2048; t += 256) {
        int mrow = t >> 4, k0 = (t & 15) << 3;
        int gr = row0 + mrow;
        float4 v0 = make_float4(0.f, 0.f, 0.f, 0.f), v1 = v0;
        if (gr < NN) {
            v0 = ((const float4*)X)[gr * 32 + (k0 >> 2)];
            v1 = ((const float4*)X)[gr * 32 + (k0 >> 2) + 1];
        }
        float f[8] = {v0.x, v0.y, v0.z, v0.w, v1.x, v1.y, v1.z, v1.w};
        __nv_bfloat162 hi[4], lo[4];
#pragma unroll
        for (int j = 0; j < 4; j++) {
            __nv_bfloat16 h0 = __float2bfloat16(f[2 * j]);
            __nv_bfloat16 h1 = __float2bfloat16(f[2 * j + 1]);
            hi[j] = __nv_bfloat162(h0, h1);
            lo[j] = __nv_bfloat162(
                __float2bfloat16(f[2 * j] - __bfloat162float(h0)),
                __float2bfloat16(f[2 * j + 1] - __bfloat162float(h1)));
        }
        unsigned off = mrow * BSTRIDE + k0 * 2;
        *(uint4*)(smem + OFF_AH + off) = *(uint4*)hi;
        *(uint4*)(smem + OFF_AL + off) = *(uint4*)lo;
    }
    __syncthreads();

    int lrow = lane & 7, lmat = lane >> 3;
    uint32_t aoff = (uint32_t)(((lmat & 1) * 8 + lrow) * BSTRIDE + (lmat >> 1) * 16);
    uint32_t boff = (uint32_t)(lrow * BSTRIDE + ((lane >> 3) & 1) * 16 +
                               (lane >> 4) * (8 * BSTRIDE));
    uint32_t aHa = sb + OFF_AH + w * 16 * BSTRIDE + aoff;
    uint32_t aLa = sb + OFF_AL + w * 16 * BSTRIDE + aoff;

    uint32_t ah[8][4], al[8][4];
#pragma unroll
    for (int s = 0; s < 8; s++) {
        LDSM4(ah[s], aHa + s * 32);
        LDSM4(al[s], aLa + s * 32);
    }

    float acc[16][4];
#pragma unroll
    for (int nt = 0; nt < 16; nt++) {
        acc[nt][0] = 0.f; acc[nt][1] = 0.f; acc[nt][2] = 0.f; acc[nt][3] = 0.f;
    }

    uint32_t bH = sb + OFF_BH + boff;
    uint32_t bL = sb + OFF_BL + boff;
#pragma unroll
    for (int p = 0; p < 8; p++) {
        uint32_t ofs = p * (16 * BSTRIDE);
#pragma unroll
        for (int s = 0; s < 8; s++) {
            uint32_t b4[4];
            LDSM4(b4, bH + ofs + s * 32);
            mma16816(acc[2 * p],     ah[s], b4);
            mma16816(acc[2 * p + 1], ah[s], b4 + 2);
            mma16816(acc[2 * p],     al[s], b4);
            mma16816(acc[2 * p + 1], al[s], b4 + 2);
        }
#pragma unroll
        for (int s = 0; s < 8; s++) {
            uint32_t b4[4];
            LDSM4(b4, bL + ofs + s * 32);
            mma16816(acc[2 * p],     ah[s], b4);
            mma16816(acc[2 * p + 1], ah[s], b4 + 2);
        }
    }

    const float* sAS = (const float*)(smem + OFF_AS);
    const float* sAD = (const float*)(smem + OFF_AD);
    int rbase = row0 + w * 16 + (lane >> 2);
#pragma unroll
    for (int rr = 0; rr < 2; rr++) {
        int m = rbase + rr * 8;
        float pss[4] = {0.f, 0.f, 0.f, 0.f};
        float pdd[4] = {0.f, 0.f, 0.f, 0.f};
#pragma unroll
        for (int nt = 0; nt < 16; nt++) {
            float c0 = acc[nt][rr * 2 + 0], c1 = acc[nt][rr * 2 + 1];
            int col = nt * 8 + (lane & 3) * 2;
            pss[nt >> 2] += c0 * sAS[col] + c1 * sAS[col + 1];
            pdd[nt >> 2] += c0 * sAD[col] + c1 * sAD[col + 1];
            if (m < NN) {
                __half2 hp = __floats2half2_rn(c0, c1);
                *(unsigned*)&g_xwh[m * 128 + col] = *(unsigned*)&hp;
            }
        }
        float mysrc = 0.f, mydst = 0.f;
#pragma unroll
        for (int j = 0; j < 4; j++) {
            float t = pss[j];
            t += __shfl_xor_sync(0xffffffffu, t, 1);
            t += __shfl_xor_sync(0xffffffffu, t, 2);
            if ((lane & 3) == j) mysrc = t;
            t = pdd[j];
            t += __shfl_xor_sync(0xffffffffu, t, 1);
            t += __shfl_xor_sync(0xffffffffu, t, 2);
            if ((lane & 3) == j) mydst = t;
        }
        if (m < NN) {
            g_ssrc[m * 4 + (lane & 3)] = mysrc;
            g_sdst[m * 4 + (lane & 3)] = mydst;
            atomicMax(&sGM[lane & 3], encf(mysrc));
        }
    }
    __syncthreads();
    if (tid < 4) atomicMax(&g_gmaxu[layer][tid], sGM[tid]);
}

// ---------------- warp-per-node single-pass softmax aggregation ------------
// mh = max(0, gmax_h + s_dst[v,h]) >= leaky(s_src[u]+s_dst[v]); shift-invariant.
template <bool LAST>
__global__ void k_agg(const float* __restrict__ bias, float* __restrict__ outp,
                      int layer) {
    int g = blockIdx.x * blockDim.x + threadIdx.x;
    int v = g >> 5, lane = g & 31;
    if (v >= NN) return;
    int offv = g_off[v];
    int deg = g_off[v + 1] - offv;
    int h2 = lane >> 3;
    float sd2 = g_sdst[v * 4 + h2];
    float mh = fmaxf(decf(g_gmaxu[layer][h2]) + sd2, 0.f);

    const uint2* XW = (const uint2*)g_xwh;

    float4 acc = make_float4(0.f, 0.f, 0.f, 0.f);
    float dsum = 0.f;
    int e = 0;
    for (; e + 8 <= deg; e += 8) {
        int u[8]; float a[8]; uint2 q[8];
#pragma unroll
        for (int j = 0; j < 8; j++) u[j] = g_csr[offv + e + j];
#pragma unroll
        for (int j = 0; j < 8; j++) a[j] = g_ssrc[u[j] * 4 + h2] + sd2;
#pragma unroll
        for (int j = 0; j < 8; j++) q[j] = XW[u[j] * 32 + lane];
#pragma unroll
        for (int j = 0; j < 8; j++) {
            float aa = (a[j] > 0.f) ? a[j] : 0.2f * a[j];
            float ex = __expf(aa - mh);
            dsum += ex;
            float x, y, z, wv;
            up4h(q[j], x, y, z, wv);
            acc.x += ex * x; acc.y += ex * y; acc.z += ex * z; acc.w += ex * wv;
        }
    }
    for (; e + 4 <= deg; e += 4) {
        int u[4]; float a[4]; uint2 q[4];
#pragma unroll
        for (int j = 0; j < 4; j++) u[j] = g_csr[offv + e + j];
#pragma unroll
        for (int j = 0; j < 4; j++) a[j] = g_ssrc[u[j] * 4 + h2] + sd2;
#pragma unroll
        for (int j = 0; j < 4; j++) q[j] = XW[u[j] * 32 + lane];
#pragma unroll
        for (int j = 0; j < 4; j++) {
            float aa = (a[j] > 0.f) ? a[j] : 0.2f * a[j];
            float ex = __expf(aa - mh);
            dsum += ex;
            float x, y, z, wv;
            up4h(q[j], x, y, z, wv);
            acc.x += ex * x; acc.y += ex * y; acc.z += ex * z; acc.w += ex * wv;
        }
    }
    for (; e < deg; e++) {
        int u = g_csr[offv + e];
        float a = g_ssrc[u * 4 + h2] + sd2;
        uint2 q = XW[u * 32 + lane];
        a = (a > 0.f) ? a : 0.2f * a;
        float ex = __expf(a - mh);
        dsum += ex;
        float x, y, z, wv;
        up4h(q, x, y, z, wv);
        acc.x += ex * x; acc.y += ex * y; acc.z += ex * z; acc.w += ex * wv;
    }
    float inv = 1.f / dsum;
    acc.x *= inv; acc.y *= inv; acc.z *= inv; acc.w *= inv;

    if (!LAST) {
        float4 bv = ((const float4*)bias)[lane];
        float4 o;
        o.x = acc.x + bv.x; o.y = acc.y + bv.y;
        o.z = acc.z + bv.z; o.w = acc.w + bv.w;
        o.x = o.x > 0.f ? o.x : expm1f(o.x);
        o.y = o.y > 0.f ? o.y : expm1f(o.y);
        o.z = o.z > 0.f ? o.z : expm1f(o.z);
        o.w = o.w > 0.f ? o.w : expm1f(o.w);
        ((float4*)g_h)[v * 32 + lane] = o;
    } else {
        acc.x += __shfl_xor_sync(0xffffffffu, acc.x, 8);
        acc.y += __shfl_xor_sync(0xffffffffu, acc.y, 8);
        acc.z += __shfl_xor_sync(0xffffffffu, acc.z, 8);
        acc.w += __shfl_xor_sync(0xffffffffu, acc.w, 8);
        acc.x += __shfl_xor_sync(0xffffffffu, acc.x, 16);
        acc.y += __shfl_xor_sync(0xffffffffu, acc.y, 16);
        acc.z += __shfl_xor_sync(0xffffffffu, acc.z, 16);
        acc.w += __shfl_xor_sync(0xffffffffu, acc.w, 16);
        if (lane < 8) {
            float4 bv = ((const float4*)bias)[lane];
            float4 o = make_float4(acc.x * 0.25f + bv.x, acc.y * 0.25f + bv.y,
                                   acc.z * 0.25f + bv.z, acc.w * 0.25f + bv.w);
            ((float4*)outp)[v * 8 + lane] = o;
        }
    }
}

// ---------------- driver ----------------------------------------------------
extern "C" void kernel_launch(void* const* d_in, const int* in_sizes, int n_in,
                              void* d_out, int out_size) {
    const float* x   = (const float*)d_in[0];
    const int*   ei  = (const int*)d_in[1];
    const float* W1  = (const float*)d_in[2];
    const float* as1 = (const float*)d_in[3];
    const float* ad1 = (const float*)d_in[4];
    const float* b1  = (const float*)d_in[5];
    const float* W2  = (const float*)d_in[6];
    const float* as2 = (const float*)d_in[7];
    const float* ad2 = (const float*)d_in[8];
    const float* b2  = (const float*)d_in[9];
    const float* W3  = (const float*)d_in[10];
    const float* as3 = (const float*)d_in[11];
    const float* ad3 = (const float*)d_in[12];
    const float* b3  = (const float*)d_in[13];
    float* out = (float*)d_out;

    cudaFuncSetAttribute(k_mm, cudaFuncAttributeMaxDynamicSharedMemorySize, SMEM_TOT);

    const int MB = (NN + 127) / 128;  // 782
    const int WB = NN / 8;            // 12500 blocks, warp per node

    // fork the CSR build onto a side stream; join before k_agg(L1)
    cudaStream_t s2;
    cudaStreamCreateWithFlags(&s2, cudaStreamNonBlocking);
    cudaEvent_t evF, evJ;
    cudaEventCreateWithFlags(&evF, cudaEventDisableTiming);
    cudaEventCreateWithFlags(&evJ, cudaEventDisableTiming);

    cudaEventRecord(evF, 0);
    cudaStreamWaitEvent(s2, evF, 0);
    k_count<<<(EE + 255) / 256, 256, 0, s2>>>(ei);
    k_scan1<<<98, 1024, 0, s2>>>();
    k_scan2<<<1, 128, 0, s2>>>();
    k_scan3<<<(NN + 255) / 256, 256, 0, s2>>>();
    k_fill<<<(ET + 255) / 256, 256, 0, s2>>>(ei);
    cudaEventRecord(evJ, s2);

    // main branch: weight prep + layer-1 GEMM in parallel with CSR
    k_prep<<<192, 256>>>(W1, W2, W3);
    k_mm<<<MB, 256, SMEM_TOT>>>(x, as1, ad1, 0);
    cudaStreamWaitEvent(0, evJ, 0);

    k_agg<false><<<WB, 256>>>(b1, nullptr, 0);

    k_mm<<<MB, 256, SMEM_TOT>>>(nullptr, as2, ad2, 1);
    k_agg<false><<<WB, 256>>>(b2, nullptr, 1);

    k_mm<<<MB, 256, SMEM_TOT>>>(nullptr, as3, ad3, 2);
    k_agg<true><<<WB, 256>>>(b3, out, 2);
}